// round 2
// baseline (speedup 1.0000x reference)
#include <cuda_runtime.h>
#include <cstdint>
#include <cstddef>

// Problem constants
#define WNUM  2048
#define NTOK  49
#define CDIM  256
#define HEADS 8
#define MROWS (WNUM * NTOK)   // 100352, divisible by 128

// Static device scratch (no runtime allocation allowed)
__device__ float g_qkv[(size_t)MROWS * 768];      // QKV GEMM output
__device__ float g_attnout[(size_t)MROWS * 256];  // attention output (pre-proj)
__device__ float g_cbias[64 * HEADS * NTOK * NTOK]; // 16*sigmoid(cpb)+mask
__device__ float g_tbl[169 * HEADS];              // CPB MLP table
__device__ float g_qkvb[768];                     // fused qkv bias
__device__ float g_krinv[WNUM * HEADS * NTOK];    // 1/||k|| per (b,h,m)

// ---------------- packed f32x2 helpers ---------------------------------------
__device__ __forceinline__ unsigned long long pack2(float x, float y) {
    unsigned long long r;
    asm("mov.b64 %0, {%1, %2};" : "=l"(r) : "f"(x), "f"(y));
    return r;
}
__device__ __forceinline__ void unpack2(unsigned long long v, float& lo, float& hi) {
    asm("mov.b64 {%0, %1}, %2;" : "=f"(lo), "=f"(hi) : "l"(v));
}
__device__ __forceinline__ void ffma2(unsigned long long& d, unsigned long long a,
                                      unsigned long long b) {
    asm("fma.rn.f32x2 %0, %1, %2, %0;" : "+l"(d) : "l"(a), "l"(b));
}

// ---------------- K1a: CPB MLP table + qkv bias vector -----------------------
__global__ void prep_kernel(const float* __restrict__ rct, const float* __restrict__ w1,
                            const float* __restrict__ b1, const float* __restrict__ w2,
                            const float* __restrict__ qb, const float* __restrict__ vb)
{
    const int tid = threadIdx.x;
    for (int c = tid; c < 768; c += 256) {
        float v = 0.f;
        if (c < 256) v = qb[c];
        else if (c >= 512) v = vb[c - 512];
        g_qkvb[c] = v;
    }
    if (tid < 169) {
        const float t0 = rct[tid * 2 + 0];
        const float t1 = rct[tid * 2 + 1];
        float s[8] = {0.f, 0.f, 0.f, 0.f, 0.f, 0.f, 0.f, 0.f};
        for (int j = 0; j < 512; j++) {
            float hval = fmaf(t0, w1[j * 2 + 0], fmaf(t1, w1[j * 2 + 1], b1[j]));
            hval = fmaxf(hval, 0.f);
            #pragma unroll
            for (int h = 0; h < 8; h++) s[h] = fmaf(hval, w2[h * 512 + j], s[h]);
        }
        #pragma unroll
        for (int h = 0; h < 8; h++) g_tbl[tid * 8 + h] = s[h];
    }
}

// ---------------- K1b: combined bias = 16*sigmoid(cpb) + mask ----------------
__global__ void bias_kernel(const int* __restrict__ rpi, const float* __restrict__ mask)
{
    const int i = blockIdx.x * 256 + threadIdx.x;
    if (i >= 64 * 8 * 2401) return;
    const int w   = i / (8 * 2401);
    const int rem = i - w * (8 * 2401);
    const int h   = rem / 2401;
    const int nm  = rem - h * 2401;
    const float t = g_tbl[rpi[nm] * 8 + h];
    const float sig = 16.f / (1.f + __expf(-t));
    g_cbias[i] = sig + mask[w * 2401 + nm];
}

// ---------------- K2/K4: NT SGEMM, 128x128x16, f32x2 packed ------------------
__global__ void __launch_bounds__(256) sgemm_nt(
    const float* __restrict__ Ap, const float* __restrict__ Bmat,
    const float* __restrict__ biasp, float* __restrict__ Cp,
    int N_, int mode)
{
    const float* A    = (mode == 0) ? Ap : g_attnout;
    const float* bias = (mode == 0) ? g_qkvb : biasp;
    float*       C    = (mode == 0) ? g_qkv : Cp;

    __shared__ __align__(16) float As[2][16][132];
    __shared__ __align__(16) float Bs[2][16][132];

    const int tid  = threadIdx.x;
    const int m0   = blockIdx.y * 128;
    const int n0   = blockIdx.x * 128;
    const int tx   = tid & 15;
    const int ty   = tid >> 4;
    const int lrow = tid >> 2;        // 0..63
    const int lkq  = (tid & 3) << 2;  // 0,4,8,12

    const float* Ab0 = A    + (size_t)(m0 + lrow) * 256 + lkq;
    const float* Ab1 = Ab0  + (size_t)64 * 256;
    const float* Bb0 = Bmat + (size_t)(n0 + lrow) * 256 + lkq;
    const float* Bb1 = Bb0  + (size_t)64 * 256;

    unsigned long long acc[8][4];
    #pragma unroll
    for (int i = 0; i < 8; i++)
        #pragma unroll
        for (int j = 0; j < 4; j++) acc[i][j] = 0ULL;

    float4 ra0, ra1, rb0, rb1;
    ra0 = *(const float4*)(Ab0);
    ra1 = *(const float4*)(Ab1);
    rb0 = *(const float4*)(Bb0);
    rb1 = *(const float4*)(Bb1);
    #pragma unroll
    for (int c = 0; c < 4; c++) {
        As[0][lkq + c][lrow]      = (&ra0.x)[c];
        As[0][lkq + c][lrow + 64] = (&ra1.x)[c];
        Bs[0][lkq + c][lrow]      = (&rb0.x)[c];
        Bs[0][lkq + c][lrow + 64] = (&rb1.x)[c];
    }
    __syncthreads();

    #pragma unroll 1
    for (int t = 0; t < 16; t++) {
        if (t < 15) {
            const int kk = (t + 1) * 16;
            ra0 = *(const float4*)(Ab0 + kk);
            ra1 = *(const float4*)(Ab1 + kk);
            rb0 = *(const float4*)(Bb0 + kk);
            rb1 = *(const float4*)(Bb1 + kk);
        }
        const int buf = t & 1;
        #pragma unroll
        for (int k = 0; k < 16; k++) {
            const float4* apt = (const float4*)&As[buf][k][ty * 8];
            const float4 a0 = apt[0], a1 = apt[1];
            const ulonglong2* bpt = (const ulonglong2*)&Bs[buf][k][tx * 8];
            const ulonglong2 bq0 = bpt[0], bq1 = bpt[1];
            const unsigned long long bb0 = bq0.x, bb1 = bq0.y, bb2 = bq1.x, bb3 = bq1.y;
            const float av[8] = {a0.x, a0.y, a0.z, a0.w, a1.x, a1.y, a1.z, a1.w};
            #pragma unroll
            for (int i = 0; i < 8; i++) {
                const unsigned long long aa = pack2(av[i], av[i]);
                ffma2(acc[i][0], aa, bb0);
                ffma2(acc[i][1], aa, bb1);
                ffma2(acc[i][2], aa, bb2);
                ffma2(acc[i][3], aa, bb3);
            }
        }
        if (t < 15) {
            const int nbuf = (t + 1) & 1;
            #pragma unroll
            for (int c = 0; c < 4; c++) {
                As[nbuf][lkq + c][lrow]      = (&ra0.x)[c];
                As[nbuf][lkq + c][lrow + 64] = (&ra1.x)[c];
                Bs[nbuf][lkq + c][lrow]      = (&rb0.x)[c];
                Bs[nbuf][lkq + c][lrow + 64] = (&rb1.x)[c];
            }
            __syncthreads();
        }
    }

    float bv[8];
    #pragma unroll
    for (int j = 0; j < 8; j++) bv[j] = bias[n0 + tx * 8 + j];
    #pragma unroll
    for (int i = 0; i < 8; i++) {
        float out[8];
        #pragma unroll
        for (int j = 0; j < 4; j++) {
            float lo, hi;
            unpack2(acc[i][j], lo, hi);
            out[2 * j]     = lo + bv[2 * j];
            out[2 * j + 1] = hi + bv[2 * j + 1];
        }
        float4* cp = (float4*)(C + (size_t)(m0 + ty * 8 + i) * N_ + n0 + tx * 8);
        cp[0] = make_float4(out[0], out[1], out[2], out[3]);
        cp[1] = make_float4(out[4], out[5], out[6], out[7]);
    }
}

// ---------------- K2b: per-row 1/||k|| ---------------------------------------
// One thread per (b,h,m): i = (b*8+h)*49+m
__global__ void __launch_bounds__(256) knorm_kernel()
{
    const int i = blockIdx.x * 256 + threadIdx.x;
    if (i >= WNUM * HEADS * NTOK) return;
    const int m  = i % NTOK;
    const int bh = i / NTOK;
    const int h  = bh % HEADS;
    const int b  = bh / HEADS;
    const float4* kp = (const float4*)(g_qkv + ((size_t)b * NTOK + m) * 768 + 256 + h * 32);
    float s0 = 0.f, s1 = 0.f, s2 = 0.f, s3 = 0.f;
    #pragma unroll
    for (int d = 0; d < 8; d++) {
        const float4 v = kp[d];
        s0 = fmaf(v.x, v.x, s0); s1 = fmaf(v.y, v.y, s1);
        s2 = fmaf(v.z, v.z, s2); s3 = fmaf(v.w, v.w, s3);
    }
    g_krinv[i] = 1.0f / fmaxf(sqrtf((s0 + s1) + (s2 + s3)), 1e-12f);
}

// ---------------- K3: window attention, thread-per-(b,h,n), no smem ----------
// K/V rows are warp-uniform addresses -> broadcast L1 hits. Logits in local.
__global__ void __launch_bounds__(256, 3) attn_kernel(const float* __restrict__ logit_scale)
{
    const int t = blockIdx.x * 256 + threadIdx.x;   // 0 .. 802815
    const int r = t % (HEADS * NTOK);
    const int b = t / (HEADS * NTOK);
    const int h = r / NTOK;
    const int n = r % NTOK;

    const size_t base = (size_t)b * NTOK * 768;

    // Load + normalize q row locally; fold per-head logit scale
    unsigned long long qq[16];
    {
        const float4* qp = (const float4*)(g_qkv + base + (size_t)n * 768 + h * 32);
        float4 qv[8];
        float s0 = 0.f, s1 = 0.f, s2 = 0.f, s3 = 0.f;
        #pragma unroll
        for (int d = 0; d < 8; d++) {
            qv[d] = qp[d];
            s0 = fmaf(qv[d].x, qv[d].x, s0); s1 = fmaf(qv[d].y, qv[d].y, s1);
            s2 = fmaf(qv[d].z, qv[d].z, s2); s3 = fmaf(qv[d].w, qv[d].w, s3);
        }
        float inv = 1.0f / fmaxf(sqrtf((s0 + s1) + (s2 + s3)), 1e-12f);
        inv *= __expf(fminf(logit_scale[h], 4.6051701859880914f)); // log(100)
        #pragma unroll
        for (int d = 0; d < 8; d++) {
            qq[2 * d]     = pack2(qv[d].x * inv, qv[d].y * inv);
            qq[2 * d + 1] = pack2(qv[d].z * inv, qv[d].w * inv);
        }
    }

    const float* cb     = g_cbias + (((size_t)(b & 63) * HEADS + h) * (NTOK * NTOK)) + n * NTOK;
    const float* krinvp = g_krinv + ((size_t)b * HEADS + h) * NTOK;

    float arow[NTOK];
    float mx = -1e30f;
    #pragma unroll 1
    for (int m = 0; m < NTOK; m++) {
        const ulonglong2* k4 = (const ulonglong2*)(g_qkv + base + (size_t)m * 768 + 256 + h * 32);
        unsigned long long a0 = 0ULL, a1 = 0ULL;
        #pragma unroll
        for (int j = 0; j < 8; j++) {
            const ulonglong2 kk = k4[j];
            ffma2(a0, qq[2 * j],     kk.x);
            ffma2(a1, qq[2 * j + 1], kk.y);
        }
        float l0, l1, l2, l3;
        unpack2(a0, l0, l1);
        unpack2(a1, l2, l3);
        const float l = ((l0 + l1) + (l2 + l3)) * krinvp[m] + cb[m];
        arow[m] = l;
        mx = fmaxf(mx, l);
    }

    float ssum = 0.f;
    #pragma unroll 1
    for (int m = 0; m < NTOK; m++) {
        const float e = __expf(arow[m] - mx);
        arow[m] = e;
        ssum += e;
    }
    const float rinv = 1.0f / ssum;

    unsigned long long o2[16];
    #pragma unroll
    for (int j = 0; j < 16; j++) o2[j] = 0ULL;
    #pragma unroll 1
    for (int m = 0; m < NTOK; m++) {
        const float pm = arow[m] * rinv;
        const unsigned long long pp = pack2(pm, pm);
        const ulonglong2* v4 = (const ulonglong2*)(g_qkv + base + (size_t)m * 768 + 512 + h * 32);
        #pragma unroll
        for (int j = 0; j < 8; j++) {
            const ulonglong2 vv = v4[j];
            ffma2(o2[2 * j],     pp, vv.x);
            ffma2(o2[2 * j + 1], pp, vv.y);
        }
    }

    float4* op = (float4*)(g_attnout + ((size_t)b * NTOK + n) * 256 + h * 32);
    #pragma unroll
    for (int d = 0; d < 8; d++) {
        float x0, x1, x2, x3;
        unpack2(o2[2 * d],     x0, x1);
        unpack2(o2[2 * d + 1], x2, x3);
        op[d] = make_float4(x0, x1, x2, x3);
    }
}

// ---------------- launch -----------------------------------------------------
extern "C" void kernel_launch(void* const* d_in, const int* in_sizes, int n_in,
                              void* d_out, int out_size)
{
    const float* x    = (const float*)d_in[0];
    const float* mask = (const float*)d_in[1];
    const float* qkvw = (const float*)d_in[2];
    const float* qb   = (const float*)d_in[3];
    const float* vb   = (const float*)d_in[4];
    const float* ls   = (const float*)d_in[5];
    const float* w1   = (const float*)d_in[6];
    const float* b1   = (const float*)d_in[7];
    const float* w2   = (const float*)d_in[8];
    const float* pw   = (const float*)d_in[9];
    const float* pb   = (const float*)d_in[10];
    const float* rct  = (const float*)d_in[11];
    const int*   rpi  = (const int*)d_in[12];
    float* out = (float*)d_out;

    prep_kernel<<<1, 256>>>(rct, w1, b1, w2, qb, vb);
    bias_kernel<<<(64 * 8 * 2401 + 255) / 256, 256>>>(rpi, mask);
    sgemm_nt<<<dim3(6, 784), 256>>>(x, qkvw, nullptr, nullptr, 768, 0);
    knorm_kernel<<<(WNUM * HEADS * NTOK + 255) / 256, 256>>>();
    attn_kernel<<<(WNUM * HEADS * NTOK) / 256, 256>>>(ls);
    sgemm_nt<<<dim3(2, 784), 256>>>(nullptr, pw, pb, out, 256, 1);
}

// round 5
// speedup vs baseline: 1.2954x; 1.2954x over previous
#include <cuda_runtime.h>
#include <cuda_bf16.h>
#include <cstdint>
#include <cstddef>

// Problem constants
#define WNUM  2048
#define NTOK  49
#define CDIM  256
#define HEADS 8
#define MROWS (WNUM * NTOK)   // 100352 = 784 * 128
#define KTOT  768             // split-K: [hi | lo | hi] x [hi | hi | lo]

// Static device scratch
__device__ float g_qkv[(size_t)MROWS * 768];
__device__ float g_attnout[(size_t)MROWS * 256];
__device__ float g_cbias[64 * HEADS * NTOK * NTOK];
__device__ float g_tbl[169 * HEADS];
__device__ float g_qkvb[768];
__device__ float g_krinv[WNUM * HEADS * NTOK];
__device__ __nv_bfloat16 g_abig[(size_t)MROWS * KTOT];  // A planes (reused qkv+proj)
__device__ __nv_bfloat16 g_bbq[768 * KTOT];             // qkv weight planes
__device__ __nv_bfloat16 g_bbp[256 * KTOT];             // proj weight planes

// ---------------- helpers -----------------------------------------------------
__device__ __forceinline__ uint32_t smem_u32(const void* p) {
    uint32_t a;
    asm("{ .reg .u64 t; cvta.to.shared.u64 t, %1; cvt.u32.u64 %0, t; }" : "=r"(a) : "l"(p));
    return a;
}
__device__ __forceinline__ void cp_async16(uint32_t s, const void* g) {
    asm volatile("cp.async.ca.shared.global [%0], [%1], 16;" :: "r"(s), "l"(g));
}
#define CP_COMMIT() asm volatile("cp.async.commit_group;" ::: "memory")
#define CP_WAIT(n)  asm volatile("cp.async.wait_group %0;" :: "n"(n) : "memory")
#define LDMX4(r, a) asm volatile( \
    "ldmatrix.sync.aligned.m8n8.x4.shared.b16 {%0,%1,%2,%3}, [%4];" \
    : "=r"((r)[0]), "=r"((r)[1]), "=r"((r)[2]), "=r"((r)[3]) : "r"(a))
#define MMA16816(c, a, b0, b1) asm volatile( \
    "mma.sync.aligned.m16n8k16.row.col.f32.bf16.bf16.f32 " \
    "{%0,%1,%2,%3},{%4,%5,%6,%7},{%8,%9},{%0,%1,%2,%3};" \
    : "+f"((c)[0]), "+f"((c)[1]), "+f"((c)[2]), "+f"((c)[3]) \
    : "r"((a)[0]), "r"((a)[1]), "r"((a)[2]), "r"((a)[3]), "r"(b0), "r"(b1))

// packed f32x2 (attention)
__device__ __forceinline__ unsigned long long pack2(float x, float y) {
    unsigned long long r;
    asm("mov.b64 %0, {%1, %2};" : "=l"(r) : "f"(x), "f"(y));
    return r;
}
__device__ __forceinline__ void unpack2(unsigned long long v, float& lo, float& hi) {
    asm("mov.b64 {%0, %1}, %2;" : "=f"(lo), "=f"(hi) : "l"(v));
}
__device__ __forceinline__ void ffma2(unsigned long long& d, unsigned long long a,
                                      unsigned long long b) {
    asm("fma.rn.f32x2 %0, %1, %2, %0;" : "+l"(d) : "l"(a), "l"(b));
}

// ---------------- K1a: CPB MLP table + qkv bias --------------------------------
__global__ void prep_kernel(const float* __restrict__ rct, const float* __restrict__ w1,
                            const float* __restrict__ b1, const float* __restrict__ w2,
                            const float* __restrict__ qb, const float* __restrict__ vb)
{
    const int tid = threadIdx.x;
    for (int c = tid; c < 768; c += 256) {
        float v = 0.f;
        if (c < 256) v = qb[c];
        else if (c >= 512) v = vb[c - 512];
        g_qkvb[c] = v;
    }
    if (tid < 169) {
        const float t0 = rct[tid * 2 + 0];
        const float t1 = rct[tid * 2 + 1];
        float s[8] = {0.f, 0.f, 0.f, 0.f, 0.f, 0.f, 0.f, 0.f};
        for (int j = 0; j < 512; j++) {
            float hval = fmaf(t0, w1[j * 2 + 0], fmaf(t1, w1[j * 2 + 1], b1[j]));
            hval = fmaxf(hval, 0.f);
            #pragma unroll
            for (int h = 0; h < 8; h++) s[h] = fmaf(hval, w2[h * 512 + j], s[h]);
        }
        #pragma unroll
        for (int h = 0; h < 8; h++) g_tbl[tid * 8 + h] = s[h];
    }
}

// ---------------- K1b: combined bias table --------------------------------------
__global__ void bias_kernel(const int* __restrict__ rpi, const float* __restrict__ mask)
{
    const int i = blockIdx.x * 256 + threadIdx.x;
    if (i >= 64 * 8 * 2401) return;
    const int w   = i / (8 * 2401);
    const int rem = i - w * (8 * 2401);
    const int h   = rem / 2401;
    const int nm  = rem - h * 2401;
    const float t = g_tbl[rpi[nm] * 8 + h];
    const float sig = 16.f / (1.f + __expf(-t));
    g_cbias[i] = sig + mask[w * 2401 + nm];
}

// ---------------- K1c: weight planes [hi | hi | lo] -----------------------------
__global__ void bconv_kernel(const float* __restrict__ qkvw, const float* __restrict__ pw)
{
    const int i = blockIdx.x * 256 + threadIdx.x;
    if (i < 768 * 256) {
        const int n = i >> 8, k = i & 255;
        const float v = qkvw[i];
        const __nv_bfloat16 h = __float2bfloat16(v);
        const __nv_bfloat16 l = __float2bfloat16(v - __bfloat162float(h));
        __nv_bfloat16* row = g_bbq + (size_t)n * KTOT;
        row[k] = h; row[256 + k] = h; row[512 + k] = l;
    }
    const int j = i - 768 * 256;
    if (j >= 0 && j < 256 * 256) {
        const int n = j >> 8, k = j & 255;
        const float v = pw[j];
        const __nv_bfloat16 h = __float2bfloat16(v);
        const __nv_bfloat16 l = __float2bfloat16(v - __bfloat162float(h));
        __nv_bfloat16* row = g_bbp + (size_t)n * KTOT;
        row[k] = h; row[256 + k] = h; row[512 + k] = l;
    }
}

// ---------------- activation planes [hi | lo | hi] ------------------------------
// mode 0: src = external x pointer; mode 1: src = g_attnout (internal symbol)
__global__ void __launch_bounds__(256) aconv_kernel(const float* __restrict__ srcp, int mode)
{
    const float* src = mode ? g_attnout : srcp;
    const int idx = blockIdx.x * 256 + threadIdx.x;   // MROWS*64
    const int m = idx >> 6, q = idx & 63;
    const float4 v = *(const float4*)(src + (size_t)m * 256 + q * 4);
    const __nv_bfloat162 h01 = __floats2bfloat162_rn(v.x, v.y);
    const __nv_bfloat162 h23 = __floats2bfloat162_rn(v.z, v.w);
    const __nv_bfloat162 l01 = __floats2bfloat162_rn(v.x - __bfloat162float(h01.x),
                                                     v.y - __bfloat162float(h01.y));
    const __nv_bfloat162 l23 = __floats2bfloat162_rn(v.z - __bfloat162float(h23.x),
                                                     v.w - __bfloat162float(h23.y));
    __nv_bfloat16* row = g_abig + (size_t)m * KTOT;
    *(__nv_bfloat162*)(row + q * 4)           = h01;
    *(__nv_bfloat162*)(row + q * 4 + 2)       = h23;
    *(__nv_bfloat162*)(row + 256 + q * 4)     = l01;
    *(__nv_bfloat162*)(row + 256 + q * 4 + 2) = l23;
    *(__nv_bfloat162*)(row + 512 + q * 4)     = h01;
    *(__nv_bfloat162*)(row + 512 + q * 4 + 2) = h23;
}

// ---------------- HMMA bf16 NT GEMM: C = A(MxK') * B(NxK')^T + bias -------------
// 128x128 tile, BK=32, 8 warps (64x32 each), cp.async double buffer.
// mode 0: B=g_bbq, bias=g_qkvb, C=g_qkv, N=768
// mode 1: B=g_bbp, bias=param,  C=param, N=256
__global__ void __launch_bounds__(256, 2) gemm_mma(
    const float* __restrict__ biasp, float* __restrict__ Cp, int mode)
{
    const __nv_bfloat16* A = g_abig;
    const __nv_bfloat16* B = mode ? g_bbp : g_bbq;
    const float* bias = mode ? biasp : g_qkvb;
    float* C = mode ? Cp : g_qkv;
    const int N = mode ? 256 : 768;

    __shared__ __nv_bfloat16 As[2][128][40];
    __shared__ __nv_bfloat16 Bs[2][128][40];

    const int tid = threadIdx.x, lane = tid & 31, wid = tid >> 5;
    const int wm = wid >> 2, wn = wid & 3;
    const int m0 = blockIdx.y * 128, n0 = blockIdx.x * 128;
    const int lrow = tid >> 2, lseg = tid & 3;

    const __nv_bfloat16* Ag = A + (size_t)(m0 + lrow) * KTOT + lseg * 8;
    const __nv_bfloat16* Bg = B + (size_t)(n0 + lrow) * KTOT + lseg * 8;

    float acc[4][4][4];
    #pragma unroll
    for (int i = 0; i < 4; i++)
        #pragma unroll
        for (int j = 0; j < 4; j++)
            #pragma unroll
            for (int r = 0; r < 4; r++) acc[i][j][r] = 0.f;

    auto load_tile = [&](int buf, int kt) {
        const __nv_bfloat16* ga = Ag + kt * 32;
        const __nv_bfloat16* gb = Bg + kt * 32;
        cp_async16(smem_u32(&As[buf][lrow][lseg * 8]), ga);
        cp_async16(smem_u32(&As[buf][lrow + 64][lseg * 8]), ga + (size_t)64 * KTOT);
        cp_async16(smem_u32(&Bs[buf][lrow][lseg * 8]), gb);
        cp_async16(smem_u32(&Bs[buf][lrow + 64][lseg * 8]), gb + (size_t)64 * KTOT);
        CP_COMMIT();
    };

    load_tile(0, 0);

    const int lr = lane & 15, lc = lane >> 4;
    const int NITER = KTOT / 32;   // 24

    for (int kt = 0; kt < NITER; kt++) {
        if (kt + 1 < NITER) {
            load_tile((kt + 1) & 1, kt + 1);
            CP_WAIT(1);
        } else {
            CP_WAIT(0);
        }
        __syncthreads();
        const int buf = kt & 1;
        #pragma unroll
        for (int kk = 0; kk < 2; kk++) {
            uint32_t af[4][4], bf[2][4];
            #pragma unroll
            for (int mi = 0; mi < 4; mi++) {
                const uint32_t a = smem_u32(&As[buf][wm * 64 + mi * 16 + lr][kk * 16 + lc * 8]);
                LDMX4(af[mi], a);
            }
            #pragma unroll
            for (int nj = 0; nj < 2; nj++) {
                const uint32_t a = smem_u32(&Bs[buf][wn * 32 + nj * 16 + lr][kk * 16 + lc * 8]);
                LDMX4(bf[nj], a);
            }
            #pragma unroll
            for (int mi = 0; mi < 4; mi++)
                #pragma unroll
                for (int nt = 0; nt < 4; nt++) {
                    const uint32_t b0 = bf[nt >> 1][nt & 1];
                    const uint32_t b1 = bf[nt >> 1][(nt & 1) + 2];
                    MMA16816(acc[mi][nt], af[mi], b0, b1);
                }
        }
        __syncthreads();
    }

    // epilogue: + bias, direct global write
    #pragma unroll
    for (int mi = 0; mi < 4; mi++) {
        #pragma unroll
        for (int nt = 0; nt < 4; nt++) {
            const int r = m0 + wm * 64 + mi * 16 + (lane >> 2);
            const int c = n0 + wn * 32 + nt * 8 + (lane & 3) * 2;
            const float b0 = bias[c], b1 = bias[c + 1];
            float* p0 = C + (size_t)r * N + c;
            float* p1 = C + (size_t)(r + 8) * N + c;
            p0[0] = acc[mi][nt][0] + b0;
            p0[1] = acc[mi][nt][1] + b1;
            p1[0] = acc[mi][nt][2] + b0;
            p1[1] = acc[mi][nt][3] + b1;
        }
    }
}

// ---------------- per-row 1/||k|| ------------------------------------------------
__global__ void __launch_bounds__(256) knorm_kernel()
{
    const int i = blockIdx.x * 256 + threadIdx.x;
    if (i >= WNUM * HEADS * NTOK) return;
    const int m  = i % NTOK;
    const int bh = i / NTOK;
    const int h  = bh % HEADS;
    const int b  = bh / HEADS;
    const float4* kp = (const float4*)(g_qkv + ((size_t)b * NTOK + m) * 768 + 256 + h * 32);
    float s0 = 0.f, s1 = 0.f, s2 = 0.f, s3 = 0.f;
    #pragma unroll
    for (int d = 0; d < 8; d++) {
        const float4 v = kp[d];
        s0 = fmaf(v.x, v.x, s0); s1 = fmaf(v.y, v.y, s1);
        s2 = fmaf(v.z, v.z, s2); s3 = fmaf(v.w, v.w, s3);
    }
    g_krinv[i] = 1.0f / fmaxf(sqrtf((s0 + s1) + (s2 + s3)), 1e-12f);
}

// ---------------- window attention (thread per (b,h,n)) ---------------------------
__global__ void __launch_bounds__(256, 3) attn_kernel(const float* __restrict__ logit_scale)
{
    const int t = blockIdx.x * 256 + threadIdx.x;
    const int r = t % (HEADS * NTOK);
    const int b = t / (HEADS * NTOK);
    const int h = r / NTOK;
    const int n = r % NTOK;

    const size_t base = (size_t)b * NTOK * 768;

    unsigned long long qq[16];
    {
        const float4* qp = (const float4*)(g_qkv + base + (size_t)n * 768 + h * 32);
        float4 qv[8];
        float s0 = 0.f, s1 = 0.f, s2 = 0.f, s3 = 0.f;
        #pragma unroll
        for (int d = 0; d < 8; d++) {
            qv[d] = qp[d];
            s0 = fmaf(qv[d].x, qv[d].x, s0); s1 = fmaf(qv[d].y, qv[d].y, s1);
            s2 = fmaf(qv[d].z, qv[d].z, s2); s3 = fmaf(qv[d].w, qv[d].w, s3);
        }
        float inv = 1.0f / fmaxf(sqrtf((s0 + s1) + (s2 + s3)), 1e-12f);
        inv *= __expf(fminf(logit_scale[h], 4.6051701859880914f));
        #pragma unroll
        for (int d = 0; d < 8; d++) {
            qq[2 * d]     = pack2(qv[d].x * inv, qv[d].y * inv);
            qq[2 * d + 1] = pack2(qv[d].z * inv, qv[d].w * inv);
        }
    }

    const float* cb     = g_cbias + (((size_t)(b & 63) * HEADS + h) * (NTOK * NTOK)) + n * NTOK;
    const float* krinvp = g_krinv + ((size_t)b * HEADS + h) * NTOK;

    float arow[NTOK];
    float mx = -1e30f;
    #pragma unroll 1
    for (int m = 0; m < NTOK; m++) {
        const ulonglong2* k4 = (const ulonglong2*)(g_qkv + base + (size_t)m * 768 + 256 + h * 32);
        unsigned long long a0 = 0ULL, a1 = 0ULL;
        #pragma unroll
        for (int j = 0; j < 8; j++) {
            const ulonglong2 kk = k4[j];
            ffma2(a0, qq[2 * j],     kk.x);
            ffma2(a1, qq[2 * j + 1], kk.y);
        }
        float l0, l1, l2, l3;
        unpack2(a0, l0, l1);
        unpack2(a1, l2, l3);
        const float l = ((l0 + l1) + (l2 + l3)) * krinvp[m] + cb[m];
        arow[m] = l;
        mx = fmaxf(mx, l);
    }

    float ssum = 0.f;
    #pragma unroll 1
    for (int m = 0; m < NTOK; m++) {
        const float e = __expf(arow[m] - mx);
        arow[m] = e;
        ssum += e;
    }
    const float rinv = 1.0f / ssum;

    unsigned long long o2[16];
    #pragma unroll
    for (int j = 0; j < 16; j++) o2[j] = 0ULL;
    #pragma unroll 1
    for (int m = 0; m < NTOK; m++) {
        const float pm = arow[m] * rinv;
        const unsigned long long pp = pack2(pm, pm);
        const ulonglong2* v4 = (const ulonglong2*)(g_qkv + base + (size_t)m * 768 + 512 + h * 32);
        #pragma unroll
        for (int j = 0; j < 8; j++) {
            const ulonglong2 vv = v4[j];
            ffma2(o2[2 * j],     pp, vv.x);
            ffma2(o2[2 * j + 1], pp, vv.y);
        }
    }

    float4* op = (float4*)(g_attnout + ((size_t)b * NTOK + n) * 256 + h * 32);
    #pragma unroll
    for (int d = 0; d < 8; d++) {
        float x0, x1, x2, x3;
        unpack2(o2[2 * d],     x0, x1);
        unpack2(o2[2 * d + 1], x2, x3);
        op[d] = make_float4(x0, x1, x2, x3);
    }
}

// ---------------- launch ----------------------------------------------------------
extern "C" void kernel_launch(void* const* d_in, const int* in_sizes, int n_in,
                              void* d_out, int out_size)
{
    const float* x    = (const float*)d_in[0];
    const float* mask = (const float*)d_in[1];
    const float* qkvw = (const float*)d_in[2];
    const float* qb   = (const float*)d_in[3];
    const float* vb   = (const float*)d_in[4];
    const float* ls   = (const float*)d_in[5];
    const float* w1   = (const float*)d_in[6];
    const float* b1   = (const float*)d_in[7];
    const float* w2   = (const float*)d_in[8];
    const float* pw   = (const float*)d_in[9];
    const float* pb   = (const float*)d_in[10];
    const float* rct  = (const float*)d_in[11];
    const int*   rpi  = (const int*)d_in[12];
    float* out = (float*)d_out;

    prep_kernel<<<1, 256>>>(rct, w1, b1, w2, qb, vb);
    bias_kernel<<<(64 * 8 * 2401 + 255) / 256, 256>>>(rpi, mask);
    bconv_kernel<<<(768 * 256 + 256 * 256) / 256, 256>>>(qkvw, pw);
    aconv_kernel<<<MROWS * 64 / 256, 256>>>(x, 0);
    gemm_mma<<<dim3(6, 784), 256>>>(nullptr, nullptr, 0);
    knorm_kernel<<<(WNUM * HEADS * NTOK + 255) / 256, 256>>>();
    attn_kernel<<<(WNUM * HEADS * NTOK) / 256, 256>>>(ls);
    aconv_kernel<<<MROWS * 64 / 256, 256>>>(nullptr, 1);
    gemm_mma<<<dim3(2, 784), 256>>>(pb, out, 1);
}

// round 6
// speedup vs baseline: 1.3743x; 1.0609x over previous
#include <cuda_runtime.h>
#include <cuda_bf16.h>
#include <cstdint>
#include <cstddef>

// Problem constants
#define WNUM  2048
#define NTOK  49
#define CDIM  256
#define HEADS 8
#define MROWS (WNUM * NTOK)   // 100352 = 784 * 128
#define KTOT  768             // split-K: [hi | lo | hi] x [hi | hi | lo]

// Static device scratch
__device__ float g_qkv[(size_t)MROWS * 768];
__device__ float g_cbias[64 * HEADS * NTOK * NTOK];   // layout [w][h][m][n] (transposed)
__device__ float g_tbl[169 * HEADS];
__device__ float g_qkvb[768];
__device__ float g_krinv[WNUM * HEADS * NTOK];
__device__ __nv_bfloat16 g_abig[(size_t)MROWS * KTOT];  // A planes (qkv input, then attn out)
__device__ __nv_bfloat16 g_bbq[768 * KTOT];             // qkv weight planes
__device__ __nv_bfloat16 g_bbp[256 * KTOT];             // proj weight planes

// ---------------- helpers -----------------------------------------------------
__device__ __forceinline__ uint32_t smem_u32(const void* p) {
    uint32_t a;
    asm("{ .reg .u64 t; cvta.to.shared.u64 t, %1; cvt.u32.u64 %0, t; }" : "=r"(a) : "l"(p));
    return a;
}
__device__ __forceinline__ void cp_async16(uint32_t s, const void* g) {
    asm volatile("cp.async.ca.shared.global [%0], [%1], 16;" :: "r"(s), "l"(g));
}
#define CP_COMMIT() asm volatile("cp.async.commit_group;" ::: "memory")
#define CP_WAIT(n)  asm volatile("cp.async.wait_group %0;" :: "n"(n) : "memory")
#define LDMX4(r, a) asm volatile( \
    "ldmatrix.sync.aligned.m8n8.x4.shared.b16 {%0,%1,%2,%3}, [%4];" \
    : "=r"((r)[0]), "=r"((r)[1]), "=r"((r)[2]), "=r"((r)[3]) : "r"(a))
#define MMA16816(c, a, b0, b1) asm volatile( \
    "mma.sync.aligned.m16n8k16.row.col.f32.bf16.bf16.f32 " \
    "{%0,%1,%2,%3},{%4,%5,%6,%7},{%8,%9},{%0,%1,%2,%3};" \
    : "+f"((c)[0]), "+f"((c)[1]), "+f"((c)[2]), "+f"((c)[3]) \
    : "r"((a)[0]), "r"((a)[1]), "r"((a)[2]), "r"((a)[3]), "r"(b0), "r"(b1))

// packed f32x2 (attention)
__device__ __forceinline__ unsigned long long pack2(float x, float y) {
    unsigned long long r;
    asm("mov.b64 %0, {%1, %2};" : "=l"(r) : "f"(x), "f"(y));
    return r;
}
__device__ __forceinline__ void unpack2(unsigned long long v, float& lo, float& hi) {
    asm("mov.b64 {%0, %1}, %2;" : "=f"(lo), "=f"(hi) : "l"(v));
}
__device__ __forceinline__ void ffma2(unsigned long long& d, unsigned long long a,
                                      unsigned long long b) {
    asm("fma.rn.f32x2 %0, %1, %2, %0;" : "+l"(d) : "l"(a), "l"(b));
}

// Fast exp on the FMA pipe (x <= 0 expected; rel err ~2e-6). Avoids MUFU.
__device__ __forceinline__ float fexp(float x) {
    float y = fmaxf(x * 1.4426950408889634f, -126.0f);
    const int n = __float2int_rn(y);
    const float f = y - (float)n;
    float p = 1.3333558e-3f;
    p = fmaf(p, f, 9.6181291e-3f);
    p = fmaf(p, f, 5.5504109e-2f);
    p = fmaf(p, f, 2.4022651e-1f);
    p = fmaf(p, f, 6.9314718e-1f);
    p = fmaf(p, f, 1.0f);
    return p * __int_as_float((n + 127) << 23);
}

// ---------------- K1a: CPB MLP table + qkv bias --------------------------------
__global__ void prep_kernel(const float* __restrict__ rct, const float* __restrict__ w1,
                            const float* __restrict__ b1, const float* __restrict__ w2,
                            const float* __restrict__ qb, const float* __restrict__ vb)
{
    const int tid = threadIdx.x;
    for (int c = tid; c < 768; c += 256) {
        float v = 0.f;
        if (c < 256) v = qb[c];
        else if (c >= 512) v = vb[c - 512];
        g_qkvb[c] = v;
    }
    if (tid < 169) {
        const float t0 = rct[tid * 2 + 0];
        const float t1 = rct[tid * 2 + 1];
        float s[8] = {0.f, 0.f, 0.f, 0.f, 0.f, 0.f, 0.f, 0.f};
        for (int j = 0; j < 512; j++) {
            float hval = fmaf(t0, w1[j * 2 + 0], fmaf(t1, w1[j * 2 + 1], b1[j]));
            hval = fmaxf(hval, 0.f);
            #pragma unroll
            for (int h = 0; h < 8; h++) s[h] = fmaf(hval, w2[h * 512 + j], s[h]);
        }
        #pragma unroll
        for (int h = 0; h < 8; h++) g_tbl[tid * 8 + h] = s[h];
    }
}

// ---------------- K1b: combined bias table, TRANSPOSED to [w][h][m][n] ----------
__global__ void bias_kernel(const int* __restrict__ rpi, const float* __restrict__ mask)
{
    const int i = blockIdx.x * 256 + threadIdx.x;
    if (i >= 64 * 8 * 2401) return;
    const int w   = i / (8 * 2401);
    const int rem = i - w * (8 * 2401);
    const int h   = rem / 2401;
    const int mn  = rem - h * 2401;
    const int m   = mn / 49;        // key index
    const int n   = mn - m * 49;    // query index
    const int nm  = n * 49 + m;     // original (query-major) flat index
    const float t = g_tbl[rpi[nm] * 8 + h];
    const float sig = 16.f / (1.f + __expf(-t));
    g_cbias[i] = sig + mask[w * 2401 + nm];
}

// ---------------- K1c: weight planes [hi | hi | lo] -----------------------------
__global__ void bconv_kernel(const float* __restrict__ qkvw, const float* __restrict__ pw)
{
    const int i = blockIdx.x * 256 + threadIdx.x;
    if (i < 768 * 256) {
        const int n = i >> 8, k = i & 255;
        const float v = qkvw[i];
        const __nv_bfloat16 h = __float2bfloat16(v);
        const __nv_bfloat16 l = __float2bfloat16(v - __bfloat162float(h));
        __nv_bfloat16* row = g_bbq + (size_t)n * KTOT;
        row[k] = h; row[256 + k] = h; row[512 + k] = l;
    }
    const int j = i - 768 * 256;
    if (j >= 0 && j < 256 * 256) {
        const int n = j >> 8, k = j & 255;
        const float v = pw[j];
        const __nv_bfloat16 h = __float2bfloat16(v);
        const __nv_bfloat16 l = __float2bfloat16(v - __bfloat162float(h));
        __nv_bfloat16* row = g_bbp + (size_t)n * KTOT;
        row[k] = h; row[256 + k] = h; row[512 + k] = l;
    }
}

// ---------------- activation planes [hi | lo | hi] from x ------------------------
__global__ void __launch_bounds__(256) aconv_kernel(const float* __restrict__ src)
{
    const int idx = blockIdx.x * 256 + threadIdx.x;   // MROWS*64
    const int m = idx >> 6, q = idx & 63;
    const float4 v = *(const float4*)(src + (size_t)m * 256 + q * 4);
    const __nv_bfloat162 h01 = __floats2bfloat162_rn(v.x, v.y);
    const __nv_bfloat162 h23 = __floats2bfloat162_rn(v.z, v.w);
    const __nv_bfloat162 l01 = __floats2bfloat162_rn(v.x - __bfloat162float(h01.x),
                                                     v.y - __bfloat162float(h01.y));
    const __nv_bfloat162 l23 = __floats2bfloat162_rn(v.z - __bfloat162float(h23.x),
                                                     v.w - __bfloat162float(h23.y));
    __nv_bfloat16* row = g_abig + (size_t)m * KTOT;
    *(__nv_bfloat162*)(row + q * 4)           = h01;
    *(__nv_bfloat162*)(row + q * 4 + 2)       = h23;
    *(__nv_bfloat162*)(row + 256 + q * 4)     = l01;
    *(__nv_bfloat162*)(row + 256 + q * 4 + 2) = l23;
    *(__nv_bfloat162*)(row + 512 + q * 4)     = h01;
    *(__nv_bfloat162*)(row + 512 + q * 4 + 2) = h23;
}

// ---------------- HMMA bf16 NT GEMM ---------------------------------------------
// mode 0: B=g_bbq, bias=g_qkvb, C=g_qkv, N=768
// mode 1: B=g_bbp, bias=param,  C=param, N=256
__global__ void __launch_bounds__(256, 2) gemm_mma(
    const float* __restrict__ biasp, float* __restrict__ Cp, int mode)
{
    const __nv_bfloat16* A = g_abig;
    const __nv_bfloat16* B = mode ? g_bbp : g_bbq;
    const float* bias = mode ? biasp : g_qkvb;
    float* C = mode ? Cp : g_qkv;
    const int N = mode ? 256 : 768;

    __shared__ __nv_bfloat16 As[2][128][40];
    __shared__ __nv_bfloat16 Bs[2][128][40];

    const int tid = threadIdx.x, lane = tid & 31, wid = tid >> 5;
    const int wm = wid >> 2, wn = wid & 3;
    const int m0 = blockIdx.y * 128, n0 = blockIdx.x * 128;
    const int lrow = tid >> 2, lseg = tid & 3;

    const __nv_bfloat16* Ag = A + (size_t)(m0 + lrow) * KTOT + lseg * 8;
    const __nv_bfloat16* Bg = B + (size_t)(n0 + lrow) * KTOT + lseg * 8;

    float acc[4][4][4];
    #pragma unroll
    for (int i = 0; i < 4; i++)
        #pragma unroll
        for (int j = 0; j < 4; j++)
            #pragma unroll
            for (int r = 0; r < 4; r++) acc[i][j][r] = 0.f;

    auto load_tile = [&](int buf, int kt) {
        const __nv_bfloat16* ga = Ag + kt * 32;
        const __nv_bfloat16* gb = Bg + kt * 32;
        cp_async16(smem_u32(&As[buf][lrow][lseg * 8]), ga);
        cp_async16(smem_u32(&As[buf][lrow + 64][lseg * 8]), ga + (size_t)64 * KTOT);
        cp_async16(smem_u32(&Bs[buf][lrow][lseg * 8]), gb);
        cp_async16(smem_u32(&Bs[buf][lrow + 64][lseg * 8]), gb + (size_t)64 * KTOT);
        CP_COMMIT();
    };

    load_tile(0, 0);

    const int lr = lane & 15, lc = lane >> 4;
    const int NITER = KTOT / 32;   // 24

    for (int kt = 0; kt < NITER; kt++) {
        if (kt + 1 < NITER) {
            load_tile((kt + 1) & 1, kt + 1);
            CP_WAIT(1);
        } else {
            CP_WAIT(0);
        }
        __syncthreads();
        const int buf = kt & 1;
        #pragma unroll
        for (int kk = 0; kk < 2; kk++) {
            uint32_t af[4][4], bf[2][4];
            #pragma unroll
            for (int mi = 0; mi < 4; mi++) {
                const uint32_t a = smem_u32(&As[buf][wm * 64 + mi * 16 + lr][kk * 16 + lc * 8]);
                LDMX4(af[mi], a);
            }
            #pragma unroll
            for (int nj = 0; nj < 2; nj++) {
                const uint32_t a = smem_u32(&Bs[buf][wn * 32 + nj * 16 + lr][kk * 16 + lc * 8]);
                LDMX4(bf[nj], a);
            }
            #pragma unroll
            for (int mi = 0; mi < 4; mi++)
                #pragma unroll
                for (int nt = 0; nt < 4; nt++) {
                    const uint32_t b0 = bf[nt >> 1][nt & 1];
                    const uint32_t b1 = bf[nt >> 1][(nt & 1) + 2];
                    MMA16816(acc[mi][nt], af[mi], b0, b1);
                }
        }
        __syncthreads();
    }

    #pragma unroll
    for (int mi = 0; mi < 4; mi++) {
        #pragma unroll
        for (int nt = 0; nt < 4; nt++) {
            const int r = m0 + wm * 64 + mi * 16 + (lane >> 2);
            const int c = n0 + wn * 32 + nt * 8 + (lane & 3) * 2;
            const float b0 = bias[c], b1 = bias[c + 1];
            float* p0 = C + (size_t)r * N + c;
            float* p1 = C + (size_t)(r + 8) * N + c;
            p0[0] = acc[mi][nt][0] + b0;
            p0[1] = acc[mi][nt][1] + b1;
            p1[0] = acc[mi][nt][2] + b0;
            p1[1] = acc[mi][nt][3] + b1;
        }
    }
}

// ---------------- per-row 1/||k|| ------------------------------------------------
__global__ void __launch_bounds__(256) knorm_kernel()
{
    const int i = blockIdx.x * 256 + threadIdx.x;
    if (i >= WNUM * HEADS * NTOK) return;
    const int m  = i % NTOK;
    const int bh = i / NTOK;
    const int h  = bh % HEADS;
    const int b  = bh / HEADS;
    const float4* kp = (const float4*)(g_qkv + ((size_t)b * NTOK + m) * 768 + 256 + h * 32);
    float s0 = 0.f, s1 = 0.f, s2 = 0.f, s3 = 0.f;
    #pragma unroll
    for (int d = 0; d < 8; d++) {
        const float4 v = kp[d];
        s0 = fmaf(v.x, v.x, s0); s1 = fmaf(v.y, v.y, s1);
        s2 = fmaf(v.z, v.z, s2); s3 = fmaf(v.w, v.w, s3);
    }
    g_krinv[i] = 1.0f / fmaxf(sqrtf((s0 + s1) + (s2 + s3)), 1e-12f);
}

// ---------------- window attention: thread per (b,h,n), smem logits --------------
// Writes the bf16 [hi|lo|hi] planes of the proj-GEMM A matrix directly.
__global__ void __launch_bounds__(256, 3) attn_kernel(const float* __restrict__ logit_scale)
{
    extern __shared__ float arow_s[];   // [256][49]
    const int t = blockIdx.x * 256 + threadIdx.x;
    const int tid = threadIdx.x;
    const int r = t % (HEADS * NTOK);
    const int b = t / (HEADS * NTOK);
    const int h = r / NTOK;
    const int n = r % NTOK;

    const size_t base = (size_t)b * NTOK * 768;
    float* arow = arow_s + tid * NTOK;

    unsigned long long qq[16];
    {
        const float4* qp = (const float4*)(g_qkv + base + (size_t)n * 768 + h * 32);
        float4 qv[8];
        float s0 = 0.f, s1 = 0.f, s2 = 0.f, s3 = 0.f;
        #pragma unroll
        for (int d = 0; d < 8; d++) {
            qv[d] = qp[d];
            s0 = fmaf(qv[d].x, qv[d].x, s0); s1 = fmaf(qv[d].y, qv[d].y, s1);
            s2 = fmaf(qv[d].z, qv[d].z, s2); s3 = fmaf(qv[d].w, qv[d].w, s3);
        }
        float inv = 1.0f / fmaxf(sqrtf((s0 + s1) + (s2 + s3)), 1e-12f);
        inv *= __expf(fminf(logit_scale[h], 4.6051701859880914f));
        #pragma unroll
        for (int d = 0; d < 8; d++) {
            qq[2 * d]     = pack2(qv[d].x * inv, qv[d].y * inv);
            qq[2 * d + 1] = pack2(qv[d].z * inv, qv[d].w * inv);
        }
    }

    // transposed bias: [w][h][m][n] -> coalesced over n
    const float* cb     = g_cbias + (((size_t)(b & 63) * HEADS + h) * (NTOK * NTOK)) + n;
    const float* krinvp = g_krinv + ((size_t)b * HEADS + h) * NTOK;

    float mx = -1e30f;
    #pragma unroll 7
    for (int m = 0; m < NTOK; m++) {
        const ulonglong2* k4 = (const ulonglong2*)(g_qkv + base + (size_t)m * 768 + 256 + h * 32);
        unsigned long long a0 = 0ULL, a1 = 0ULL;
        #pragma unroll
        for (int j = 0; j < 8; j++) {
            const ulonglong2 kk = k4[j];
            ffma2(a0, qq[2 * j],     kk.x);
            ffma2(a1, qq[2 * j + 1], kk.y);
        }
        float l0, l1, l2, l3;
        unpack2(a0, l0, l1);
        unpack2(a1, l2, l3);
        const float l = ((l0 + l1) + (l2 + l3)) * krinvp[m] + cb[m * NTOK];
        arow[m] = l;
        mx = fmaxf(mx, l);
    }

    float ssum = 0.f;
    #pragma unroll 7
    for (int m = 0; m < NTOK; m++) {
        const float e = fexp(arow[m] - mx);
        arow[m] = e;
        ssum += e;
    }
    const float rinv = 1.0f / ssum;

    unsigned long long o2[16];
    #pragma unroll
    for (int j = 0; j < 16; j++) o2[j] = 0ULL;
    #pragma unroll 7
    for (int m = 0; m < NTOK; m++) {
        const float pm = arow[m] * rinv;
        const unsigned long long pp = pack2(pm, pm);
        const ulonglong2* v4 = (const ulonglong2*)(g_qkv + base + (size_t)m * 768 + 512 + h * 32);
        #pragma unroll
        for (int j = 0; j < 8; j++) {
            const ulonglong2 vv = v4[j];
            ffma2(o2[2 * j],     pp, vv.x);
            ffma2(o2[2 * j + 1], pp, vv.y);
        }
    }

    // write bf16 [hi|lo|hi] planes directly into the proj GEMM's A matrix
    __nv_bfloat16* rowp = g_abig + ((size_t)b * NTOK + n) * KTOT;
    uint32_t hv[16], lv[16];
    #pragma unroll
    for (int d = 0; d < 8; d++) {
        float x0, x1, x2, x3;
        unpack2(o2[2 * d],     x0, x1);
        unpack2(o2[2 * d + 1], x2, x3);
        const __nv_bfloat162 h01 = __floats2bfloat162_rn(x0, x1);
        const __nv_bfloat162 h23 = __floats2bfloat162_rn(x2, x3);
        const __nv_bfloat162 l01 = __floats2bfloat162_rn(x0 - __bfloat162float(h01.x),
                                                         x1 - __bfloat162float(h01.y));
        const __nv_bfloat162 l23 = __floats2bfloat162_rn(x2 - __bfloat162float(h23.x),
                                                         x3 - __bfloat162float(h23.y));
        hv[2 * d]     = *(const uint32_t*)&h01;
        hv[2 * d + 1] = *(const uint32_t*)&h23;
        lv[2 * d]     = *(const uint32_t*)&l01;
        lv[2 * d + 1] = *(const uint32_t*)&l23;
    }
    #pragma unroll
    for (int i = 0; i < 4; i++) {
        uint4 vh = make_uint4(hv[4 * i], hv[4 * i + 1], hv[4 * i + 2], hv[4 * i + 3]);
        uint4 vl = make_uint4(lv[4 * i], lv[4 * i + 1], lv[4 * i + 2], lv[4 * i + 3]);
        *(uint4*)(rowp + h * 32 + i * 8)       = vh;
        *(uint4*)(rowp + 256 + h * 32 + i * 8) = vl;
        *(uint4*)(rowp + 512 + h * 32 + i * 8) = vh;
    }
}

// ---------------- launch ----------------------------------------------------------
extern "C" void kernel_launch(void* const* d_in, const int* in_sizes, int n_in,
                              void* d_out, int out_size)
{
    const float* x    = (const float*)d_in[0];
    const float* mask = (const float*)d_in[1];
    const float* qkvw = (const float*)d_in[2];
    const float* qb   = (const float*)d_in[3];
    const float* vb   = (const float*)d_in[4];
    const float* ls   = (const float*)d_in[5];
    const float* w1   = (const float*)d_in[6];
    const float* b1   = (const float*)d_in[7];
    const float* w2   = (const float*)d_in[8];
    const float* pw   = (const float*)d_in[9];
    const float* pb   = (const float*)d_in[10];
    const float* rct  = (const float*)d_in[11];
    const int*   rpi  = (const int*)d_in[12];
    float* out = (float*)d_out;

    const int attn_smem = 256 * NTOK * 4;   // 50176 B
    cudaFuncSetAttribute(attn_kernel, cudaFuncAttributeMaxDynamicSharedMemorySize, attn_smem);

    prep_kernel<<<1, 256>>>(rct, w1, b1, w2, qb, vb);
    bias_kernel<<<(64 * 8 * 2401 + 255) / 256, 256>>>(rpi, mask);
    bconv_kernel<<<(768 * 256 + 256 * 256) / 256, 256>>>(qkvw, pw);
    aconv_kernel<<<MROWS * 64 / 256, 256>>>(x);
    gemm_mma<<<dim3(6, 784), 256>>>(nullptr, nullptr, 0);
    knorm_kernel<<<(WNUM * HEADS * NTOK + 255) / 256, 256>>>();
    attn_kernel<<<(WNUM * HEADS * NTOK) / 256, 256, attn_smem>>>(ls);
    gemm_mma<<<dim3(2, 784), 256>>>(pb, out, 1);
}

// round 7
// speedup vs baseline: 1.6006x; 1.1647x over previous
#include <cuda_runtime.h>
#include <cuda_bf16.h>
#include <cstdint>
#include <cstddef>

// Problem constants
#define WNUM  2048
#define NTOK  49
#define CDIM  256
#define HEADS 8
#define MROWS (WNUM * NTOK)   // 100352 = 784 * 128
#define KTOT  768             // split-K: [hi | lo | hi] x [hi | hi | lo]

// Static device scratch
__device__ float g_qkv[(size_t)MROWS * 768];
__device__ float g_cbias[64 * HEADS * NTOK * NTOK];   // layout [w][h][m][n]
__device__ float g_tbl[169 * HEADS];
__device__ float g_qkvb[768];
__device__ __nv_bfloat16 g_abig[(size_t)MROWS * KTOT];  // A planes (qkv input, then attn out)
__device__ __nv_bfloat16 g_bbq[768 * KTOT];             // qkv weight planes
__device__ __nv_bfloat16 g_bbp[256 * KTOT];             // proj weight planes

// ---------------- helpers -----------------------------------------------------
__device__ __forceinline__ uint32_t smem_u32(const void* p) {
    uint32_t a;
    asm("{ .reg .u64 t; cvta.to.shared.u64 t, %1; cvt.u32.u64 %0, t; }" : "=r"(a) : "l"(p));
    return a;
}
__device__ __forceinline__ void cp_async16(uint32_t s, const void* g) {
    asm volatile("cp.async.ca.shared.global [%0], [%1], 16;" :: "r"(s), "l"(g));
}
#define CP_COMMIT() asm volatile("cp.async.commit_group;" ::: "memory")
#define CP_WAIT(n)  asm volatile("cp.async.wait_group %0;" :: "n"(n) : "memory")
#define LDMX4(r, a) asm volatile( \
    "ldmatrix.sync.aligned.m8n8.x4.shared.b16 {%0,%1,%2,%3}, [%4];" \
    : "=r"((r)[0]), "=r"((r)[1]), "=r"((r)[2]), "=r"((r)[3]) : "r"(a))
#define MMA16816(c, a, b0, b1) asm volatile( \
    "mma.sync.aligned.m16n8k16.row.col.f32.bf16.bf16.f32 " \
    "{%0,%1,%2,%3},{%4,%5,%6,%7},{%8,%9},{%0,%1,%2,%3};" \
    : "+f"((c)[0]), "+f"((c)[1]), "+f"((c)[2]), "+f"((c)[3]) \
    : "r"((a)[0]), "r"((a)[1]), "r"((a)[2]), "r"((a)[3]), "r"(b0), "r"(b1))

// packed f32x2 (attention)
__device__ __forceinline__ unsigned long long pack2(float x, float y) {
    unsigned long long r;
    asm("mov.b64 %0, {%1, %2};" : "=l"(r) : "f"(x), "f"(y));
    return r;
}
__device__ __forceinline__ void unpack2(unsigned long long v, float& lo, float& hi) {
    asm("mov.b64 {%0, %1}, %2;" : "=f"(lo), "=f"(hi) : "l"(v));
}
__device__ __forceinline__ void ffma2(unsigned long long& d, unsigned long long a,
                                      unsigned long long b) {
    asm("fma.rn.f32x2 %0, %1, %2, %0;" : "+l"(d) : "l"(a), "l"(b));
}

// Fast exp on the FMA pipe (x <= 0 expected; rel err ~2e-6). Avoids MUFU.
__device__ __forceinline__ float fexp(float x) {
    float y = fmaxf(x * 1.4426950408889634f, -126.0f);
    const int n = __float2int_rn(y);
    const float f = y - (float)n;
    float p = 1.3333558e-3f;
    p = fmaf(p, f, 9.6181291e-3f);
    p = fmaf(p, f, 5.5504109e-2f);
    p = fmaf(p, f, 2.4022651e-1f);
    p = fmaf(p, f, 6.9314718e-1f);
    p = fmaf(p, f, 1.0f);
    return p * __int_as_float((n + 127) << 23);
}

// ---------------- K1a: CPB MLP table + qkv bias --------------------------------
__global__ void prep_kernel(const float* __restrict__ rct, const float* __restrict__ w1,
                            const float* __restrict__ b1, const float* __restrict__ w2,
                            const float* __restrict__ qb, const float* __restrict__ vb)
{
    const int tid = threadIdx.x;
    for (int c = tid; c < 768; c += 256) {
        float v = 0.f;
        if (c < 256) v = qb[c];
        else if (c >= 512) v = vb[c - 512];
        g_qkvb[c] = v;
    }
    if (tid < 169) {
        const float t0 = rct[tid * 2 + 0];
        const float t1 = rct[tid * 2 + 1];
        float s[8] = {0.f, 0.f, 0.f, 0.f, 0.f, 0.f, 0.f, 0.f};
        for (int j = 0; j < 512; j++) {
            float hval = fmaf(t0, w1[j * 2 + 0], fmaf(t1, w1[j * 2 + 1], b1[j]));
            hval = fmaxf(hval, 0.f);
            #pragma unroll
            for (int h = 0; h < 8; h++) s[h] = fmaf(hval, w2[h * 512 + j], s[h]);
        }
        #pragma unroll
        for (int h = 0; h < 8; h++) g_tbl[tid * 8 + h] = s[h];
    }
}

// ---------------- K1b: combined bias table, layout [w][h][m][n] ------------------
__global__ void bias_kernel(const int* __restrict__ rpi, const float* __restrict__ mask)
{
    const int i = blockIdx.x * 256 + threadIdx.x;
    if (i >= 64 * 8 * 2401) return;
    const int w   = i / (8 * 2401);
    const int rem = i - w * (8 * 2401);
    const int h   = rem / 2401;
    const int mn  = rem - h * 2401;
    const int m   = mn / 49;        // key index
    const int n   = mn - m * 49;    // query index
    const int nm  = n * 49 + m;     // original (query-major) flat index
    const float t = g_tbl[rpi[nm] * 8 + h];
    const float sig = 16.f / (1.f + __expf(-t));
    g_cbias[i] = sig + mask[w * 2401 + nm];
}

// ---------------- K1c: weight planes [hi | hi | lo] -----------------------------
__global__ void bconv_kernel(const float* __restrict__ qkvw, const float* __restrict__ pw)
{
    const int i = blockIdx.x * 256 + threadIdx.x;
    if (i < 768 * 256) {
        const int n = i >> 8, k = i & 255;
        const float v = qkvw[i];
        const __nv_bfloat16 h = __float2bfloat16(v);
        const __nv_bfloat16 l = __float2bfloat16(v - __bfloat162float(h));
        __nv_bfloat16* row = g_bbq + (size_t)n * KTOT;
        row[k] = h; row[256 + k] = h; row[512 + k] = l;
    }
    const int j = i - 768 * 256;
    if (j >= 0 && j < 256 * 256) {
        const int n = j >> 8, k = j & 255;
        const float v = pw[j];
        const __nv_bfloat16 h = __float2bfloat16(v);
        const __nv_bfloat16 l = __float2bfloat16(v - __bfloat162float(h));
        __nv_bfloat16* row = g_bbp + (size_t)n * KTOT;
        row[k] = h; row[256 + k] = h; row[512 + k] = l;
    }
}

// ---------------- activation planes [hi | lo | hi] from x ------------------------
__global__ void __launch_bounds__(256) aconv_kernel(const float* __restrict__ src)
{
    const int idx = blockIdx.x * 256 + threadIdx.x;   // MROWS*64
    const int m = idx >> 6, q = idx & 63;
    const float4 v = *(const float4*)(src + (size_t)m * 256 + q * 4);
    const __nv_bfloat162 h01 = __floats2bfloat162_rn(v.x, v.y);
    const __nv_bfloat162 h23 = __floats2bfloat162_rn(v.z, v.w);
    const __nv_bfloat162 l01 = __floats2bfloat162_rn(v.x - __bfloat162float(h01.x),
                                                     v.y - __bfloat162float(h01.y));
    const __nv_bfloat162 l23 = __floats2bfloat162_rn(v.z - __bfloat162float(h23.x),
                                                     v.w - __bfloat162float(h23.y));
    __nv_bfloat16* row = g_abig + (size_t)m * KTOT;
    *(__nv_bfloat162*)(row + q * 4)           = h01;
    *(__nv_bfloat162*)(row + q * 4 + 2)       = h23;
    *(__nv_bfloat162*)(row + 256 + q * 4)     = l01;
    *(__nv_bfloat162*)(row + 256 + q * 4 + 2) = l23;
    *(__nv_bfloat162*)(row + 512 + q * 4)     = h01;
    *(__nv_bfloat162*)(row + 512 + q * 4 + 2) = h23;
}

// ---------------- HMMA bf16 NT GEMM ---------------------------------------------
// mode 0: B=g_bbq, bias=g_qkvb, C=g_qkv, N=768
// mode 1: B=g_bbp, bias=param,  C=param, N=256
__global__ void __launch_bounds__(256, 2) gemm_mma(
    const float* __restrict__ biasp, float* __restrict__ Cp, int mode)
{
    const __nv_bfloat16* A = g_abig;
    const __nv_bfloat16* B = mode ? g_bbp : g_bbq;
    const float* bias = mode ? biasp : g_qkvb;
    float* C = mode ? Cp : g_qkv;
    const int N = mode ? 256 : 768;

    __shared__ __nv_bfloat16 As[2][128][40];
    __shared__ __nv_bfloat16 Bs[2][128][40];

    const int tid = threadIdx.x, lane = tid & 31, wid = tid >> 5;
    const int wm = wid >> 2, wn = wid & 3;
    const int m0 = blockIdx.y * 128, n0 = blockIdx.x * 128;
    const int lrow = tid >> 2, lseg = tid & 3;

    const __nv_bfloat16* Ag = A + (size_t)(m0 + lrow) * KTOT + lseg * 8;
    const __nv_bfloat16* Bg = B + (size_t)(n0 + lrow) * KTOT + lseg * 8;

    float acc[4][4][4];
    #pragma unroll
    for (int i = 0; i < 4; i++)
        #pragma unroll
        for (int j = 0; j < 4; j++)
            #pragma unroll
            for (int r = 0; r < 4; r++) acc[i][j][r] = 0.f;

    auto load_tile = [&](int buf, int kt) {
        const __nv_bfloat16* ga = Ag + kt * 32;
        const __nv_bfloat16* gb = Bg + kt * 32;
        cp_async16(smem_u32(&As[buf][lrow][lseg * 8]), ga);
        cp_async16(smem_u32(&As[buf][lrow + 64][lseg * 8]), ga + (size_t)64 * KTOT);
        cp_async16(smem_u32(&Bs[buf][lrow][lseg * 8]), gb);
        cp_async16(smem_u32(&Bs[buf][lrow + 64][lseg * 8]), gb + (size_t)64 * KTOT);
        CP_COMMIT();
    };

    load_tile(0, 0);

    const int lr = lane & 15, lc = lane >> 4;
    const int NITER = KTOT / 32;   // 24

    for (int kt = 0; kt < NITER; kt++) {
        if (kt + 1 < NITER) {
            load_tile((kt + 1) & 1, kt + 1);
            CP_WAIT(1);
        } else {
            CP_WAIT(0);
        }
        __syncthreads();
        const int buf = kt & 1;
        #pragma unroll
        for (int kk = 0; kk < 2; kk++) {
            uint32_t af[4][4], bf[2][4];
            #pragma unroll
            for (int mi = 0; mi < 4; mi++) {
                const uint32_t a = smem_u32(&As[buf][wm * 64 + mi * 16 + lr][kk * 16 + lc * 8]);
                LDMX4(af[mi], a);
            }
            #pragma unroll
            for (int nj = 0; nj < 2; nj++) {
                const uint32_t a = smem_u32(&Bs[buf][wn * 32 + nj * 16 + lr][kk * 16 + lc * 8]);
                LDMX4(bf[nj], a);
            }
            #pragma unroll
            for (int mi = 0; mi < 4; mi++)
                #pragma unroll
                for (int nt = 0; nt < 4; nt++) {
                    const uint32_t b0 = bf[nt >> 1][nt & 1];
                    const uint32_t b1 = bf[nt >> 1][(nt & 1) + 2];
                    MMA16816(acc[mi][nt], af[mi], b0, b1);
                }
        }
        __syncthreads();
    }

    #pragma unroll
    for (int mi = 0; mi < 4; mi++) {
        #pragma unroll
        for (int nt = 0; nt < 4; nt++) {
            const int r = m0 + wm * 64 + mi * 16 + (lane >> 2);
            const int c = n0 + wn * 32 + nt * 8 + (lane & 3) * 2;
            const float b0 = bias[c], b1 = bias[c + 1];
            float* p0 = C + (size_t)r * N + c;
            float* p1 = C + (size_t)(r + 8) * N + c;
            p0[0] = acc[mi][nt][0] + b0;
            p0[1] = acc[mi][nt][1] + b1;
            p1[0] = acc[mi][nt][2] + b0;
            p1[1] = acc[mi][nt][3] + b1;
        }
    }
}

// ---------------- window attention: CTA per (window, 4-head group) ---------------
// Stage K,V fp32 in smem; krinv computed in-CTA; K/V reads are broadcast LDS.
// smem floats: Ks 6272 | Vs 6272 | Krs 196 | arow 196*49  => 22344 floats (89376 B)
#define ATT_THREADS 224
#define ATT_SMEMF   (6272 + 6272 + 196 + 196 * 49)
__global__ void __launch_bounds__(ATT_THREADS, 2) attn_kernel(const float* __restrict__ logit_scale)
{
    extern __shared__ float sm[];
    float* Ks   = sm;
    float* Vs   = sm + 6272;
    float* Krs  = sm + 12544;
    float* arowb = sm + 12740;

    const int tid = threadIdx.x;
    const int b   = blockIdx.x >> 1;
    const int hb  = (blockIdx.x & 1) * 4;     // head group base
    const size_t base = (size_t)b * NTOK * 768;

    // stage K,V for 4 heads (49 rows x 128 floats each), coalesced 512B rows
    {
        const float* gk = g_qkv + base + 256 + hb * 32;
        const float* gv = g_qkv + base + 512 + hb * 32;
        #pragma unroll
        for (int i = 0; i < 7; i++) {
            const int f = tid + i * ATT_THREADS;   // 0..1567
            const int m = f >> 5, q = (f & 31) * 4;
            *(float4*)(Ks + m * 128 + q) = *(const float4*)(gk + (size_t)m * 768 + q);
            *(float4*)(Vs + m * 128 + q) = *(const float4*)(gv + (size_t)m * 768 + q);
        }
    }
    __syncthreads();

    // 1/||k|| per (h,m)
    if (tid < 196) {
        const int h = tid / NTOK, m = tid - (tid / NTOK) * NTOK;
        const float4* kp = (const float4*)(Ks + m * 128 + h * 32);
        float s0 = 0.f, s1 = 0.f, s2 = 0.f, s3 = 0.f;
        #pragma unroll
        for (int d = 0; d < 8; d++) {
            const float4 v = kp[d];
            s0 = fmaf(v.x, v.x, s0); s1 = fmaf(v.y, v.y, s1);
            s2 = fmaf(v.z, v.z, s2); s3 = fmaf(v.w, v.w, s3);
        }
        Krs[tid] = 1.0f / fmaxf(sqrtf((s0 + s1) + (s2 + s3)), 1e-12f);
    }
    __syncthreads();

    if (tid < 196) {
        const int h = tid / NTOK;
        const int n = tid - h * NTOK;
        const int hg = hb + h;

        // q: load from global, normalize, fold logit scale
        unsigned long long qq[16];
        {
            const float4* qp = (const float4*)(g_qkv + base + (size_t)n * 768 + hg * 32);
            float4 qv[8];
            float s0 = 0.f, s1 = 0.f, s2 = 0.f, s3 = 0.f;
            #pragma unroll
            for (int d = 0; d < 8; d++) {
                qv[d] = qp[d];
                s0 = fmaf(qv[d].x, qv[d].x, s0); s1 = fmaf(qv[d].y, qv[d].y, s1);
                s2 = fmaf(qv[d].z, qv[d].z, s2); s3 = fmaf(qv[d].w, qv[d].w, s3);
            }
            float inv = 1.0f / fmaxf(sqrtf((s0 + s1) + (s2 + s3)), 1e-12f);
            inv *= __expf(fminf(logit_scale[hg], 4.6051701859880914f));
            #pragma unroll
            for (int d = 0; d < 8; d++) {
                qq[2 * d]     = pack2(qv[d].x * inv, qv[d].y * inv);
                qq[2 * d + 1] = pack2(qv[d].z * inv, qv[d].w * inv);
            }
        }

        const float* cb = g_cbias + (((size_t)(b & 63) * HEADS + hg) * (NTOK * NTOK)) + n;
        const float* krp = Krs + h * NTOK;
        float* arow = arowb + tid * NTOK;

        float mx = -1e30f;
        #pragma unroll 7
        for (int m = 0; m < NTOK; m++) {
            const ulonglong2* k4 = (const ulonglong2*)(Ks + m * 128 + h * 32);
            unsigned long long a0 = 0ULL, a1 = 0ULL;
            #pragma unroll
            for (int j = 0; j < 8; j++) {
                const ulonglong2 kk = k4[j];
                ffma2(a0, qq[2 * j],     kk.x);
                ffma2(a1, qq[2 * j + 1], kk.y);
            }
            float l0, l1, l2, l3;
            unpack2(a0, l0, l1);
            unpack2(a1, l2, l3);
            const float l = ((l0 + l1) + (l2 + l3)) * krp[m] + cb[m * NTOK];
            arow[m] = l;
            mx = fmaxf(mx, l);
        }

        float ssum = 0.f;
        #pragma unroll 7
        for (int m = 0; m < NTOK; m++) {
            const float e = fexp(arow[m] - mx);
            arow[m] = e;
            ssum += e;
        }
        const float rinv = 1.0f / ssum;

        unsigned long long o2[16];
        #pragma unroll
        for (int j = 0; j < 16; j++) o2[j] = 0ULL;
        #pragma unroll 7
        for (int m = 0; m < NTOK; m++) {
            const float pm = arow[m] * rinv;
            const unsigned long long pp = pack2(pm, pm);
            const ulonglong2* v4 = (const ulonglong2*)(Vs + m * 128 + h * 32);
            #pragma unroll
            for (int j = 0; j < 8; j++) {
                const ulonglong2 vv = v4[j];
                ffma2(o2[2 * j],     pp, vv.x);
                ffma2(o2[2 * j + 1], pp, vv.y);
            }
        }

        // write bf16 [hi|lo|hi] planes directly into the proj GEMM's A matrix
        __nv_bfloat16* rowp = g_abig + ((size_t)b * NTOK + n) * KTOT;
        uint32_t hv[16], lv[16];
        #pragma unroll
        for (int d = 0; d < 8; d++) {
            float x0, x1, x2, x3;
            unpack2(o2[2 * d],     x0, x1);
            unpack2(o2[2 * d + 1], x2, x3);
            const __nv_bfloat162 h01 = __floats2bfloat162_rn(x0, x1);
            const __nv_bfloat162 h23 = __floats2bfloat162_rn(x2, x3);
            const __nv_bfloat162 l01 = __floats2bfloat162_rn(x0 - __bfloat162float(h01.x),
                                                             x1 - __bfloat162float(h01.y));
            const __nv_bfloat162 l23 = __floats2bfloat162_rn(x2 - __bfloat162float(h23.x),
                                                             x3 - __bfloat162float(h23.y));
            hv[2 * d]     = *(const uint32_t*)&h01;
            hv[2 * d + 1] = *(const uint32_t*)&h23;
            lv[2 * d]     = *(const uint32_t*)&l01;
            lv[2 * d + 1] = *(const uint32_t*)&l23;
        }
        #pragma unroll
        for (int i = 0; i < 4; i++) {
            uint4 vh = make_uint4(hv[4 * i], hv[4 * i + 1], hv[4 * i + 2], hv[4 * i + 3]);
            uint4 vl = make_uint4(lv[4 * i], lv[4 * i + 1], lv[4 * i + 2], lv[4 * i + 3]);
            *(uint4*)(rowp + hg * 32 + i * 8)       = vh;
            *(uint4*)(rowp + 256 + hg * 32 + i * 8) = vl;
            *(uint4*)(rowp + 512 + hg * 32 + i * 8) = vh;
        }
    }
}

// ---------------- launch ----------------------------------------------------------
extern "C" void kernel_launch(void* const* d_in, const int* in_sizes, int n_in,
                              void* d_out, int out_size)
{
    const float* x    = (const float*)d_in[0];
    const float* mask = (const float*)d_in[1];
    const float* qkvw = (const float*)d_in[2];
    const float* qb   = (const float*)d_in[3];
    const float* vb   = (const float*)d_in[4];
    const float* ls   = (const float*)d_in[5];
    const float* w1   = (const float*)d_in[6];
    const float* b1   = (const float*)d_in[7];
    const float* w2   = (const float*)d_in[8];
    const float* pw   = (const float*)d_in[9];
    const float* pb   = (const float*)d_in[10];
    const float* rct  = (const float*)d_in[11];
    const int*   rpi  = (const int*)d_in[12];
    float* out = (float*)d_out;

    const int attn_smem = ATT_SMEMF * 4;   // 89376 B
    cudaFuncSetAttribute(attn_kernel, cudaFuncAttributeMaxDynamicSharedMemorySize, attn_smem);

    // Launch order puts the QKV GEMM at position 4 (the launch ncu captures).
    prep_kernel<<<1, 256>>>(rct, w1, b1, w2, qb, vb);
    bconv_kernel<<<(768 * 256 + 256 * 256) / 256, 256>>>(qkvw, pw);
    aconv_kernel<<<MROWS * 64 / 256, 256>>>(x);
    gemm_mma<<<dim3(6, 784), 256>>>(nullptr, nullptr, 0);            // <- profiled
    bias_kernel<<<(64 * 8 * 2401 + 255) / 256, 256>>>(rpi, mask);
    attn_kernel<<<WNUM * 2, ATT_THREADS, attn_smem>>>(ls);
    gemm_mma<<<dim3(2, 784), 256>>>(pb, out, 1);
}

// round 8
// speedup vs baseline: 1.6290x; 1.0177x over previous
#include <cuda_runtime.h>
#include <cuda_bf16.h>
#include <cstdint>
#include <cstddef>

// Problem constants
#define WNUM  2048
#define NTOK  49
#define CDIM  256
#define HEADS 8
#define MROWS (WNUM * NTOK)   // 100352 = 784 * 128
#define KTOT  768             // split-K: [hi | lo | hi] x [hi | hi | lo]

// Static device scratch
__device__ float g_qkv[(size_t)MROWS * 768];
__device__ float g_cbias[64 * HEADS * NTOK * NTOK];   // layout [w][h][m][n]
__device__ float g_tbl[169 * HEADS];
__device__ float g_qkvb[768];
__device__ __nv_bfloat16 g_abig[(size_t)MROWS * KTOT];
__device__ __nv_bfloat16 g_bbq[768 * KTOT];
__device__ __nv_bfloat16 g_bbp[256 * KTOT];

// ---------------- helpers -----------------------------------------------------
__device__ __forceinline__ uint32_t smem_u32(const void* p) {
    uint32_t a;
    asm("{ .reg .u64 t; cvta.to.shared.u64 t, %1; cvt.u32.u64 %0, t; }" : "=r"(a) : "l"(p));
    return a;
}
__device__ __forceinline__ void cp_async16(uint32_t s, const void* g) {
    asm volatile("cp.async.ca.shared.global [%0], [%1], 16;" :: "r"(s), "l"(g));
}
#define CP_COMMIT() asm volatile("cp.async.commit_group;" ::: "memory")
#define CP_WAIT(n)  asm volatile("cp.async.wait_group %0;" :: "n"(n) : "memory")
#define LDMX4(r, a) asm volatile( \
    "ldmatrix.sync.aligned.m8n8.x4.shared.b16 {%0,%1,%2,%3}, [%4];" \
    : "=r"((r)[0]), "=r"((r)[1]), "=r"((r)[2]), "=r"((r)[3]) : "r"(a))
#define MMA16816(c, a, b0, b1) asm volatile( \
    "mma.sync.aligned.m16n8k16.row.col.f32.bf16.bf16.f32 " \
    "{%0,%1,%2,%3},{%4,%5,%6,%7},{%8,%9},{%0,%1,%2,%3};" \
    : "+f"((c)[0]), "+f"((c)[1]), "+f"((c)[2]), "+f"((c)[3]) \
    : "r"((a)[0]), "r"((a)[1]), "r"((a)[2]), "r"((a)[3]), "r"(b0), "r"(b1))

// XOR-swizzled 16B-chunk address within a [128][32]-bf16 tile (64B rows).
// Conflict-free for both cp.async writes and ldmatrix phase reads.
__device__ __forceinline__ uint32_t swz(int row, int chunk) {
    return (uint32_t)(row * 64 + ((chunk ^ ((row >> 1) & 3)) << 4));
}

// packed f32x2 (attention)
__device__ __forceinline__ unsigned long long pack2(float x, float y) {
    unsigned long long r;
    asm("mov.b64 %0, {%1, %2};" : "=l"(r) : "f"(x), "f"(y));
    return r;
}
__device__ __forceinline__ void unpack2(unsigned long long v, float& lo, float& hi) {
    asm("mov.b64 {%0, %1}, %2;" : "=f"(lo), "=f"(hi) : "l"(v));
}
__device__ __forceinline__ void ffma2(unsigned long long& d, unsigned long long a,
                                      unsigned long long b) {
    asm("fma.rn.f32x2 %0, %1, %2, %0;" : "+l"(d) : "l"(a), "l"(b));
}

// Fast exp on the FMA pipe (x <= 0 expected; rel err ~2e-6). Avoids MUFU.
__device__ __forceinline__ float fexp(float x) {
    float y = fmaxf(x * 1.4426950408889634f, -126.0f);
    const int n = __float2int_rn(y);
    const float f = y - (float)n;
    float p = 1.3333558e-3f;
    p = fmaf(p, f, 9.6181291e-3f);
    p = fmaf(p, f, 5.5504109e-2f);
    p = fmaf(p, f, 2.4022651e-1f);
    p = fmaf(p, f, 6.9314718e-1f);
    p = fmaf(p, f, 1.0f);
    return p * __int_as_float((n + 127) << 23);
}

// ---------------- K1: CPB MLP table + qkv bias ----------------------------------
__global__ void prep_kernel(const float* __restrict__ rct, const float* __restrict__ w1,
                            const float* __restrict__ b1, const float* __restrict__ w2,
                            const float* __restrict__ qb, const float* __restrict__ vb)
{
    const int tid = threadIdx.x;
    for (int c = tid; c < 768; c += 256) {
        float v = 0.f;
        if (c < 256) v = qb[c];
        else if (c >= 512) v = vb[c - 512];
        g_qkvb[c] = v;
    }
    if (tid < 169) {
        const float t0 = rct[tid * 2 + 0];
        const float t1 = rct[tid * 2 + 1];
        float s[8] = {0.f, 0.f, 0.f, 0.f, 0.f, 0.f, 0.f, 0.f};
        for (int j = 0; j < 512; j++) {
            float hval = fmaf(t0, w1[j * 2 + 0], fmaf(t1, w1[j * 2 + 1], b1[j]));
            hval = fmaxf(hval, 0.f);
            #pragma unroll
            for (int h = 0; h < 8; h++) s[h] = fmaf(hval, w2[h * 512 + j], s[h]);
        }
        #pragma unroll
        for (int h = 0; h < 8; h++) g_tbl[tid * 8 + h] = s[h];
    }
}

// ---------------- K2: merged activation + weight conversion ---------------------
// blocks [0, 25088): activation planes [hi|lo|hi] from x
// blocks [25088, 26112): weight planes [hi|hi|lo] for qkvw and pw
__global__ void __launch_bounds__(256) conv_kernel(
    const float* __restrict__ x, const float* __restrict__ qkvw, const float* __restrict__ pw)
{
    const int blk = blockIdx.x;
    const int tid = threadIdx.x;
    if (blk < 25088) {
        const int idx = blk * 256 + tid;
        const int m = idx >> 6, q = idx & 63;
        const float4 v = *(const float4*)(x + (size_t)m * 256 + q * 4);
        const __nv_bfloat162 h01 = __floats2bfloat162_rn(v.x, v.y);
        const __nv_bfloat162 h23 = __floats2bfloat162_rn(v.z, v.w);
        const __nv_bfloat162 l01 = __floats2bfloat162_rn(v.x - __bfloat162float(h01.x),
                                                         v.y - __bfloat162float(h01.y));
        const __nv_bfloat162 l23 = __floats2bfloat162_rn(v.z - __bfloat162float(h23.x),
                                                         v.w - __bfloat162float(h23.y));
        __nv_bfloat16* row = g_abig + (size_t)m * KTOT;
        *(__nv_bfloat162*)(row + q * 4)           = h01;
        *(__nv_bfloat162*)(row + q * 4 + 2)       = h23;
        *(__nv_bfloat162*)(row + 256 + q * 4)     = l01;
        *(__nv_bfloat162*)(row + 256 + q * 4 + 2) = l23;
        *(__nv_bfloat162*)(row + 512 + q * 4)     = h01;
        *(__nv_bfloat162*)(row + 512 + q * 4 + 2) = h23;
    } else {
        const int i = (blk - 25088) * 256 + tid;
        if (i < 768 * 256) {
            const int n = i >> 8, k = i & 255;
            const float v = qkvw[i];
            const __nv_bfloat16 h = __float2bfloat16(v);
            const __nv_bfloat16 l = __float2bfloat16(v - __bfloat162float(h));
            __nv_bfloat16* row = g_bbq + (size_t)n * KTOT;
            row[k] = h; row[256 + k] = h; row[512 + k] = l;
        }
        const int j = i - 768 * 256;
        if (j >= 0 && j < 256 * 256) {
            const int n = j >> 8, k = j & 255;
            const float v = pw[j];
            const __nv_bfloat16 h = __float2bfloat16(v);
            const __nv_bfloat16 l = __float2bfloat16(v - __bfloat162float(h));
            __nv_bfloat16* row = g_bbp + (size_t)n * KTOT;
            row[k] = h; row[256 + k] = h; row[512 + k] = l;
        }
    }
}

// ---------------- K3/K5: HMMA bf16 NT GEMM (swizzled smem) ----------------------
// mode 0: B=g_bbq, bias=g_qkvb, C=g_qkv, N=768; tail blocks run the cbias table.
// mode 1: B=g_bbp, bias=param,  C=param, N=256
__global__ void __launch_bounds__(256, 2) gemm_mma(
    const float* __restrict__ biasp, float* __restrict__ Cp, int mode,
    const int* __restrict__ rpi, const float* __restrict__ mask)
{
    const int NX = mode ? 2 : 6;
    const int ngemm = NX * 784;
    const int gx = blockIdx.x;
    const int tid = threadIdx.x;

    if (gx >= ngemm) {   // cbias tail (mode 0 only): [w][h][m][n] combined table
        const int i = (gx - ngemm) * 256 + tid;
        if (i < 64 * 8 * 2401) {
            const int w   = i / (8 * 2401);
            const int rem = i - w * (8 * 2401);
            const int h   = rem / 2401;
            const int mn  = rem - h * 2401;
            const int m   = mn / 49;
            const int n   = mn - m * 49;
            const int nm  = n * 49 + m;
            const float t = g_tbl[rpi[nm] * 8 + h];
            const float sig = 16.f / (1.f + __expf(-t));
            g_cbias[i] = sig + mask[w * 2401 + nm];
        }
        return;
    }

    const __nv_bfloat16* A = g_abig;
    const __nv_bfloat16* B = mode ? g_bbp : g_bbq;
    const float* bias = mode ? biasp : g_qkvb;
    float* C = mode ? Cp : g_qkv;
    const int N = mode ? 256 : 768;

    __shared__ __nv_bfloat16 As[2][128][32];
    __shared__ __nv_bfloat16 Bs[2][128][32];

    const int lane = tid & 31, wid = tid >> 5;
    const int wm = wid >> 2, wn = wid & 3;
    const int m0 = (gx / NX) * 128, n0 = (gx % NX) * 128;
    const int lrow = tid >> 2, lseg = tid & 3;

    const __nv_bfloat16* Ag = A + (size_t)(m0 + lrow) * KTOT + lseg * 8;
    const __nv_bfloat16* Bg = B + (size_t)(n0 + lrow) * KTOT + lseg * 8;

    float acc[4][4][4];
    #pragma unroll
    for (int i = 0; i < 4; i++)
        #pragma unroll
        for (int j = 0; j < 4; j++)
            #pragma unroll
            for (int r = 0; r < 4; r++) acc[i][j][r] = 0.f;

    auto load_tile = [&](int buf, int kt) {
        const __nv_bfloat16* ga = Ag + kt * 32;
        const __nv_bfloat16* gb = Bg + kt * 32;
        const uint32_t sA = smem_u32(&As[buf][0][0]);
        const uint32_t sB = smem_u32(&Bs[buf][0][0]);
        cp_async16(sA + swz(lrow, lseg), ga);
        cp_async16(sA + swz(lrow + 64, lseg), ga + (size_t)64 * KTOT);
        cp_async16(sB + swz(lrow, lseg), gb);
        cp_async16(sB + swz(lrow + 64, lseg), gb + (size_t)64 * KTOT);
        CP_COMMIT();
    };

    load_tile(0, 0);

    const int lr = lane & 15, lc = lane >> 4;
    const int NITER = KTOT / 32;   // 24

    for (int kt = 0; kt < NITER; kt++) {
        if (kt + 1 < NITER) {
            load_tile((kt + 1) & 1, kt + 1);
            CP_WAIT(1);
        } else {
            CP_WAIT(0);
        }
        __syncthreads();
        const int buf = kt & 1;
        const uint32_t sA = smem_u32(&As[buf][0][0]);
        const uint32_t sB = smem_u32(&Bs[buf][0][0]);
        #pragma unroll
        for (int kk = 0; kk < 2; kk++) {
            uint32_t af[4][4], bf[2][4];
            #pragma unroll
            for (int mi = 0; mi < 4; mi++)
                LDMX4(af[mi], sA + swz(wm * 64 + mi * 16 + lr, kk * 2 + lc));
            #pragma unroll
            for (int nj = 0; nj < 2; nj++)
                LDMX4(bf[nj], sB + swz(wn * 32 + nj * 16 + lr, kk * 2 + lc));
            #pragma unroll
            for (int mi = 0; mi < 4; mi++)
                #pragma unroll
                for (int nt = 0; nt < 4; nt++) {
                    const uint32_t b0 = bf[nt >> 1][nt & 1];
                    const uint32_t b1 = bf[nt >> 1][(nt & 1) + 2];
                    MMA16816(acc[mi][nt], af[mi], b0, b1);
                }
        }
        __syncthreads();
    }

    #pragma unroll
    for (int mi = 0; mi < 4; mi++) {
        #pragma unroll
        for (int nt = 0; nt < 4; nt++) {
            const int r = m0 + wm * 64 + mi * 16 + (lane >> 2);
            const int c = n0 + wn * 32 + nt * 8 + (lane & 3) * 2;
            const float b0 = bias[c], b1 = bias[c + 1];
            float* p0 = C + (size_t)r * N + c;
            float* p1 = C + (size_t)(r + 8) * N + c;
            p0[0] = acc[mi][nt][0] + b0;
            p0[1] = acc[mi][nt][1] + b1;
            p1[0] = acc[mi][nt][2] + b0;
            p1[1] = acc[mi][nt][3] + b1;
        }
    }
}

// ---------------- K4: window attention, CTA per (window, 4-head group) ----------
// Fused softmax: exp + sum + AV in one pass; 1/S applied at the end.
#define ATT_THREADS 224
#define ATT_SMEMF   (6272 + 6272 + 196 + 196 * 49)
__global__ void __launch_bounds__(ATT_THREADS, 2) attn_kernel(const float* __restrict__ logit_scale)
{
    extern __shared__ float sm[];
    float* Ks    = sm;
    float* Vs    = sm + 6272;
    float* Krs   = sm + 12544;
    float* arowb = sm + 12740;

    const int tid = threadIdx.x;
    const int b   = blockIdx.x >> 1;
    const int hb  = (blockIdx.x & 1) * 4;
    const size_t base = (size_t)b * NTOK * 768;

    {
        const float* gk = g_qkv + base + 256 + hb * 32;
        const float* gv = g_qkv + base + 512 + hb * 32;
        #pragma unroll
        for (int i = 0; i < 7; i++) {
            const int f = tid + i * ATT_THREADS;
            const int m = f >> 5, q = (f & 31) * 4;
            *(float4*)(Ks + m * 128 + q) = *(const float4*)(gk + (size_t)m * 768 + q);
            *(float4*)(Vs + m * 128 + q) = *(const float4*)(gv + (size_t)m * 768 + q);
        }
    }
    __syncthreads();

    if (tid < 196) {
        const int h = tid / NTOK, m = tid - (tid / NTOK) * NTOK;
        const float4* kp = (const float4*)(Ks + m * 128 + h * 32);
        float s0 = 0.f, s1 = 0.f, s2 = 0.f, s3 = 0.f;
        #pragma unroll
        for (int d = 0; d < 8; d++) {
            const float4 v = kp[d];
            s0 = fmaf(v.x, v.x, s0); s1 = fmaf(v.y, v.y, s1);
            s2 = fmaf(v.z, v.z, s2); s3 = fmaf(v.w, v.w, s3);
        }
        Krs[tid] = 1.0f / fmaxf(sqrtf((s0 + s1) + (s2 + s3)), 1e-12f);
    }
    __syncthreads();

    if (tid < 196) {
        const int h = tid / NTOK;
        const int n = tid - h * NTOK;
        const int hg = hb + h;

        unsigned long long qq[16];
        {
            const float4* qp = (const float4*)(g_qkv + base + (size_t)n * 768 + hg * 32);
            float4 qv[8];
            float s0 = 0.f, s1 = 0.f, s2 = 0.f, s3 = 0.f;
            #pragma unroll
            for (int d = 0; d < 8; d++) {
                qv[d] = qp[d];
                s0 = fmaf(qv[d].x, qv[d].x, s0); s1 = fmaf(qv[d].y, qv[d].y, s1);
                s2 = fmaf(qv[d].z, qv[d].z, s2); s3 = fmaf(qv[d].w, qv[d].w, s3);
            }
            float inv = 1.0f / fmaxf(sqrtf((s0 + s1) + (s2 + s3)), 1e-12f);
            inv *= __expf(fminf(logit_scale[hg], 4.6051701859880914f));
            #pragma unroll
            for (int d = 0; d < 8; d++) {
                qq[2 * d]     = pack2(qv[d].x * inv, qv[d].y * inv);
                qq[2 * d + 1] = pack2(qv[d].z * inv, qv[d].w * inv);
            }
        }

        const float* cb  = g_cbias + (((size_t)(b & 63) * HEADS + hg) * (NTOK * NTOK)) + n;
        const float* krp = Krs + h * NTOK;
        float* arow = arowb + tid * NTOK;

        float mx = -1e30f;
        #pragma unroll 7
        for (int m = 0; m < NTOK; m++) {
            const ulonglong2* k4 = (const ulonglong2*)(Ks + m * 128 + h * 32);
            unsigned long long a0 = 0ULL, a1 = 0ULL;
            #pragma unroll
            for (int j = 0; j < 8; j++) {
                const ulonglong2 kk = k4[j];
                ffma2(a0, qq[2 * j],     kk.x);
                ffma2(a1, qq[2 * j + 1], kk.y);
            }
            float l0, l1, l2, l3;
            unpack2(a0, l0, l1);
            unpack2(a1, l2, l3);
            const float l = ((l0 + l1) + (l2 + l3)) * krp[m] + cb[m * NTOK];
            arow[m] = l;
            mx = fmaxf(mx, l);
        }

        // fused: exp + sum + AV accumulate; divide by S at the end
        float ssum = 0.f;
        unsigned long long o2[16];
        #pragma unroll
        for (int j = 0; j < 16; j++) o2[j] = 0ULL;
        #pragma unroll 7
        for (int m = 0; m < NTOK; m++) {
            const float e = fexp(arow[m] - mx);
            ssum += e;
            const unsigned long long pp = pack2(e, e);
            const ulonglong2* v4 = (const ulonglong2*)(Vs + m * 128 + h * 32);
            #pragma unroll
            for (int j = 0; j < 8; j++) {
                const ulonglong2 vv = v4[j];
                ffma2(o2[2 * j],     pp, vv.x);
                ffma2(o2[2 * j + 1], pp, vv.y);
            }
        }
        const float rinv = 1.0f / ssum;

        __nv_bfloat16* rowp = g_abig + ((size_t)b * NTOK + n) * KTOT;
        uint32_t hv[16], lv[16];
        #pragma unroll
        for (int d = 0; d < 8; d++) {
            float x0, x1, x2, x3;
            unpack2(o2[2 * d],     x0, x1);
            unpack2(o2[2 * d + 1], x2, x3);
            x0 *= rinv; x1 *= rinv; x2 *= rinv; x3 *= rinv;
            const __nv_bfloat162 h01 = __floats2bfloat162_rn(x0, x1);
            const __nv_bfloat162 h23 = __floats2bfloat162_rn(x2, x3);
            const __nv_bfloat162 l01 = __floats2bfloat162_rn(x0 - __bfloat162float(h01.x),
                                                             x1 - __bfloat162float(h01.y));
            const __nv_bfloat162 l23 = __floats2bfloat162_rn(x2 - __bfloat162float(h23.x),
                                                             x3 - __bfloat162float(h23.y));
            hv[2 * d]     = *(const uint32_t*)&h01;
            hv[2 * d + 1] = *(const uint32_t*)&h23;
            lv[2 * d]     = *(const uint32_t*)&l01;
            lv[2 * d + 1] = *(const uint32_t*)&l23;
        }
        #pragma unroll
        for (int i = 0; i < 4; i++) {
            uint4 vh = make_uint4(hv[4 * i], hv[4 * i + 1], hv[4 * i + 2], hv[4 * i + 3]);
            uint4 vl = make_uint4(lv[4 * i], lv[4 * i + 1], lv[4 * i + 2], lv[4 * i + 3]);
            *(uint4*)(rowp + hg * 32 + i * 8)       = vh;
            *(uint4*)(rowp + 256 + hg * 32 + i * 8) = vl;
            *(uint4*)(rowp + 512 + hg * 32 + i * 8) = vh;
        }
    }
}

// ---------------- launch ----------------------------------------------------------
extern "C" void kernel_launch(void* const* d_in, const int* in_sizes, int n_in,
                              void* d_out, int out_size)
{
    const float* x    = (const float*)d_in[0];
    const float* mask = (const float*)d_in[1];
    const float* qkvw = (const float*)d_in[2];
    const float* qb   = (const float*)d_in[3];
    const float* vb   = (const float*)d_in[4];
    const float* ls   = (const float*)d_in[5];
    const float* w1   = (const float*)d_in[6];
    const float* b1   = (const float*)d_in[7];
    const float* w2   = (const float*)d_in[8];
    const float* pw   = (const float*)d_in[9];
    const float* pb   = (const float*)d_in[10];
    const float* rct  = (const float*)d_in[11];
    const int*   rpi  = (const int*)d_in[12];
    float* out = (float*)d_out;

    const int attn_smem = ATT_SMEMF * 4;   // 89376 B
    cudaFuncSetAttribute(attn_kernel, cudaFuncAttributeMaxDynamicSharedMemorySize, attn_smem);

    const int nbias = (64 * 8 * 2401 + 255) / 256;   // 6003 tail blocks

    prep_kernel<<<1, 256>>>(rct, w1, b1, w2, qb, vb);
    conv_kernel<<<25088 + 1024, 256>>>(x, qkvw, pw);
    gemm_mma<<<6 * 784 + nbias, 256>>>(nullptr, nullptr, 0, rpi, mask);
    attn_kernel<<<WNUM * 2, ATT_THREADS, attn_smem>>>(ls);          // <- profiled
    gemm_mma<<<2 * 784, 256>>>(pb, out, 1, nullptr, nullptr);
}

// round 9
// speedup vs baseline: 1.7745x; 1.0893x over previous
#include <cuda_runtime.h>
#include <cuda_bf16.h>
#include <cstdint>
#include <cstddef>

// Problem constants
#define WNUM  2048
#define NTOK  49
#define CDIM  256
#define HEADS 8
#define MROWS (WNUM * NTOK)   // 100352 = 784 * 128
#define KTOT  768             // split-K: [hi | lo | hi] x [hi | hi | lo]

// Static device scratch
__device__ float g_qkv[(size_t)MROWS * 768];
__device__ float g_cbias[64 * HEADS * NTOK * 50];     // layout [w][h][m][n-pad50]
__device__ float g_tbl[169 * HEADS];
__device__ float g_qkvb[768];
__device__ __nv_bfloat16 g_abig[(size_t)MROWS * KTOT];
__device__ __nv_bfloat16 g_bbq[768 * KTOT];
__device__ __nv_bfloat16 g_bbp[256 * KTOT];

// ---------------- helpers -----------------------------------------------------
__device__ __forceinline__ uint32_t smem_u32(const void* p) {
    uint32_t a;
    asm("{ .reg .u64 t; cvta.to.shared.u64 t, %1; cvt.u32.u64 %0, t; }" : "=r"(a) : "l"(p));
    return a;
}
__device__ __forceinline__ void cp_async16(uint32_t s, const void* g) {
    asm volatile("cp.async.ca.shared.global [%0], [%1], 16;" :: "r"(s), "l"(g));
}
#define CP_COMMIT() asm volatile("cp.async.commit_group;" ::: "memory")
#define CP_WAIT(n)  asm volatile("cp.async.wait_group %0;" :: "n"(n) : "memory")
#define LDMX4(r, a) asm volatile( \
    "ldmatrix.sync.aligned.m8n8.x4.shared.b16 {%0,%1,%2,%3}, [%4];" \
    : "=r"((r)[0]), "=r"((r)[1]), "=r"((r)[2]), "=r"((r)[3]) : "r"(a))
#define MMA16816(c, a, b0, b1) asm volatile( \
    "mma.sync.aligned.m16n8k16.row.col.f32.bf16.bf16.f32 " \
    "{%0,%1,%2,%3},{%4,%5,%6,%7},{%8,%9},{%0,%1,%2,%3};" \
    : "+f"((c)[0]), "+f"((c)[1]), "+f"((c)[2]), "+f"((c)[3]) \
    : "r"((a)[0]), "r"((a)[1]), "r"((a)[2]), "r"((a)[3]), "r"(b0), "r"(b1))

// XOR-swizzled 16B-chunk address within a [128][32]-bf16 tile (64B rows).
__device__ __forceinline__ uint32_t swz(int row, int chunk) {
    return (uint32_t)(row * 64 + ((chunk ^ ((row >> 1) & 3)) << 4));
}

// packed f32x2 (attention)
__device__ __forceinline__ unsigned long long pack2(float x, float y) {
    unsigned long long r;
    asm("mov.b64 %0, {%1, %2};" : "=l"(r) : "f"(x), "f"(y));
    return r;
}
__device__ __forceinline__ void unpack2(unsigned long long v, float& lo, float& hi) {
    asm("mov.b64 {%0, %1}, %2;" : "=f"(lo), "=f"(hi) : "l"(v));
}
__device__ __forceinline__ void ffma2(unsigned long long& d, unsigned long long a,
                                      unsigned long long b) {
    asm("fma.rn.f32x2 %0, %1, %2, %0;" : "+l"(d) : "l"(a), "l"(b));
}

// Fast exp on the FMA pipe (rel err ~2e-6). Avoids MUFU.
__device__ __forceinline__ float fexp(float x) {
    float y = fmaxf(x * 1.4426950408889634f, -126.0f);
    const int n = __float2int_rn(y);
    const float f = y - (float)n;
    float p = 1.3333558e-3f;
    p = fmaf(p, f, 9.6181291e-3f);
    p = fmaf(p, f, 5.5504109e-2f);
    p = fmaf(p, f, 2.4022651e-1f);
    p = fmaf(p, f, 6.9314718e-1f);
    p = fmaf(p, f, 1.0f);
    return p * __int_as_float((n + 127) << 23);
}

// ---------------- K1: CPB MLP table + qkv bias ----------------------------------
__global__ void prep_kernel(const float* __restrict__ rct, const float* __restrict__ w1,
                            const float* __restrict__ b1, const float* __restrict__ w2,
                            const float* __restrict__ qb, const float* __restrict__ vb)
{
    const int tid = threadIdx.x;
    for (int c = tid; c < 768; c += 256) {
        float v = 0.f;
        if (c < 256) v = qb[c];
        else if (c >= 512) v = vb[c - 512];
        g_qkvb[c] = v;
    }
    if (tid < 169) {
        const float t0 = rct[tid * 2 + 0];
        const float t1 = rct[tid * 2 + 1];
        float s[8] = {0.f, 0.f, 0.f, 0.f, 0.f, 0.f, 0.f, 0.f};
        for (int j = 0; j < 512; j++) {
            float hval = fmaf(t0, w1[j * 2 + 0], fmaf(t1, w1[j * 2 + 1], b1[j]));
            hval = fmaxf(hval, 0.f);
            #pragma unroll
            for (int h = 0; h < 8; h++) s[h] = fmaf(hval, w2[h * 512 + j], s[h]);
        }
        #pragma unroll
        for (int h = 0; h < 8; h++) g_tbl[tid * 8 + h] = s[h];
    }
}

// ---------------- K2: merged activation + weight conversion ---------------------
__global__ void __launch_bounds__(256) conv_kernel(
    const float* __restrict__ x, const float* __restrict__ qkvw, const float* __restrict__ pw)
{
    const int blk = blockIdx.x;
    const int tid = threadIdx.x;
    if (blk < 25088) {
        const int idx = blk * 256 + tid;
        const int m = idx >> 6, q = idx & 63;
        const float4 v = *(const float4*)(x + (size_t)m * 256 + q * 4);
        const __nv_bfloat162 h01 = __floats2bfloat162_rn(v.x, v.y);
        const __nv_bfloat162 h23 = __floats2bfloat162_rn(v.z, v.w);
        const __nv_bfloat162 l01 = __floats2bfloat162_rn(v.x - __bfloat162float(h01.x),
                                                         v.y - __bfloat162float(h01.y));
        const __nv_bfloat162 l23 = __floats2bfloat162_rn(v.z - __bfloat162float(h23.x),
                                                         v.w - __bfloat162float(h23.y));
        __nv_bfloat16* row = g_abig + (size_t)m * KTOT;
        *(__nv_bfloat162*)(row + q * 4)           = h01;
        *(__nv_bfloat162*)(row + q * 4 + 2)       = h23;
        *(__nv_bfloat162*)(row + 256 + q * 4)     = l01;
        *(__nv_bfloat162*)(row + 256 + q * 4 + 2) = l23;
        *(__nv_bfloat162*)(row + 512 + q * 4)     = h01;
        *(__nv_bfloat162*)(row + 512 + q * 4 + 2) = h23;
    } else {
        const int i = (blk - 25088) * 256 + tid;
        if (i < 768 * 256) {
            const int n = i >> 8, k = i & 255;
            const float v = qkvw[i];
            const __nv_bfloat16 h = __float2bfloat16(v);
            const __nv_bfloat16 l = __float2bfloat16(v - __bfloat162float(h));
            __nv_bfloat16* row = g_bbq + (size_t)n * KTOT;
            row[k] = h; row[256 + k] = h; row[512 + k] = l;
        }
        const int j = i - 768 * 256;
        if (j >= 0 && j < 256 * 256) {
            const int n = j >> 8, k = j & 255;
            const float v = pw[j];
            const __nv_bfloat16 h = __float2bfloat16(v);
            const __nv_bfloat16 l = __float2bfloat16(v - __bfloat162float(h));
            __nv_bfloat16* row = g_bbp + (size_t)n * KTOT;
            row[k] = h; row[256 + k] = h; row[512 + k] = l;
        }
    }
}

// ---------------- K3/K5: HMMA bf16 NT GEMM (swizzled smem) ----------------------
// mode 0: B=g_bbq, bias=g_qkvb, C=g_qkv, N=768; tail blocks build the cbias table.
// mode 1: B=g_bbp, bias=param,  C=param, N=256
__global__ void __launch_bounds__(256, 2) gemm_mma(
    const float* __restrict__ biasp, float* __restrict__ Cp, int mode,
    const int* __restrict__ rpi, const float* __restrict__ mask)
{
    const int NX = mode ? 2 : 6;
    const int ngemm = NX * 784;
    const int gx = blockIdx.x;
    const int tid = threadIdx.x;

    if (gx >= ngemm) {   // cbias tail (mode 0 only): [w][h][m][n-pad50]
        const int i = (gx - ngemm) * 256 + tid;
        if (i < 64 * 8 * 49 * 50) {
            const int w   = i / (8 * 2450);
            const int rem = i - w * (8 * 2450);
            const int h   = rem / 2450;
            const int mn  = rem - h * 2450;
            const int m   = mn / 50;        // key index
            const int n   = mn - m * 50;    // query index (49 = pad)
            float val = 0.f;
            if (n < 49) {
                const int nm = n * 49 + m;
                const float t = g_tbl[rpi[nm] * 8 + h];
                val = 16.f / (1.f + __expf(-t)) + mask[w * 2401 + nm];
            }
            g_cbias[i] = val;
        }
        return;
    }

    const __nv_bfloat16* A = g_abig;
    const __nv_bfloat16* B = mode ? g_bbp : g_bbq;
    const float* bias = mode ? biasp : g_qkvb;
    float* C = mode ? Cp : g_qkv;
    const int N = mode ? 256 : 768;

    __shared__ __nv_bfloat16 As[2][128][32];
    __shared__ __nv_bfloat16 Bs[2][128][32];

    const int lane = tid & 31, wid = tid >> 5;
    const int wm = wid >> 2, wn = wid & 3;
    const int m0 = (gx / NX) * 128, n0 = (gx % NX) * 128;
    const int lrow = tid >> 2, lseg = tid & 3;

    const __nv_bfloat16* Ag = A + (size_t)(m0 + lrow) * KTOT + lseg * 8;
    const __nv_bfloat16* Bg = B + (size_t)(n0 + lrow) * KTOT + lseg * 8;

    float acc[4][4][4];
    #pragma unroll
    for (int i = 0; i < 4; i++)
        #pragma unroll
        for (int j = 0; j < 4; j++)
            #pragma unroll
            for (int r = 0; r < 4; r++) acc[i][j][r] = 0.f;

    auto load_tile = [&](int buf, int kt) {
        const __nv_bfloat16* ga = Ag + kt * 32;
        const __nv_bfloat16* gb = Bg + kt * 32;
        const uint32_t sA = smem_u32(&As[buf][0][0]);
        const uint32_t sB = smem_u32(&Bs[buf][0][0]);
        cp_async16(sA + swz(lrow, lseg), ga);
        cp_async16(sA + swz(lrow + 64, lseg), ga + (size_t)64 * KTOT);
        cp_async16(sB + swz(lrow, lseg), gb);
        cp_async16(sB + swz(lrow + 64, lseg), gb + (size_t)64 * KTOT);
        CP_COMMIT();
    };

    load_tile(0, 0);

    const int lr = lane & 15, lc = lane >> 4;
    const int NITER = KTOT / 32;   // 24

    for (int kt = 0; kt < NITER; kt++) {
        if (kt + 1 < NITER) {
            load_tile((kt + 1) & 1, kt + 1);
            CP_WAIT(1);
        } else {
            CP_WAIT(0);
        }
        __syncthreads();
        const int buf = kt & 1;
        const uint32_t sA = smem_u32(&As[buf][0][0]);
        const uint32_t sB = smem_u32(&Bs[buf][0][0]);
        #pragma unroll
        for (int kk = 0; kk < 2; kk++) {
            uint32_t af[4][4], bf[2][4];
            #pragma unroll
            for (int mi = 0; mi < 4; mi++)
                LDMX4(af[mi], sA + swz(wm * 64 + mi * 16 + lr, kk * 2 + lc));
            #pragma unroll
            for (int nj = 0; nj < 2; nj++)
                LDMX4(bf[nj], sB + swz(wn * 32 + nj * 16 + lr, kk * 2 + lc));
            #pragma unroll
            for (int mi = 0; mi < 4; mi++)
                #pragma unroll
                for (int nt = 0; nt < 4; nt++) {
                    const uint32_t b0 = bf[nt >> 1][nt & 1];
                    const uint32_t b1 = bf[nt >> 1][(nt & 1) + 2];
                    MMA16816(acc[mi][nt], af[mi], b0, b1);
                }
        }
        __syncthreads();
    }

    #pragma unroll
    for (int mi = 0; mi < 4; mi++) {
        #pragma unroll
        for (int nt = 0; nt < 4; nt++) {
            const int r = m0 + wm * 64 + mi * 16 + (lane >> 2);
            const int c = n0 + wn * 32 + nt * 8 + (lane & 3) * 2;
            const float b0 = bias[c], b1 = bias[c + 1];
            float* p0 = C + (size_t)r * N + c;
            float* p1 = C + (size_t)(r + 8) * N + c;
            p0[0] = acc[mi][nt][0] + b0;
            p0[1] = acc[mi][nt][1] + b1;
            p1[0] = acc[mi][nt][2] + b0;
            p1[1] = acc[mi][nt][3] + b1;
        }
    }
}

// ---------------- K4: window attention ------------------------------------------
// Thread = (query-pair, d-half): K/V smem reads amortized over 2 queries,
// partner-lane shfl combines the half-d partial dot products.
#define ATT_THREADS 224
#define ATT_SMEMF   (6272 + 6272 + 196 + 200 * 49)
__global__ void __launch_bounds__(ATT_THREADS, 2) attn_kernel(const float* __restrict__ logit_scale)
{
    extern __shared__ float sm[];
    float* Ks    = sm;
    float* Vs    = sm + 6272;
    float* Krs   = sm + 12544;
    float* arowb = sm + 12740;

    const int tid = threadIdx.x;
    const int b   = blockIdx.x >> 1;
    const int hb  = (blockIdx.x & 1) * 4;
    const size_t base = (size_t)b * NTOK * 768;

    // stage K,V for 4 heads (49 rows x 128 floats each)
    {
        const float* gk = g_qkv + base + 256 + hb * 32;
        const float* gv = g_qkv + base + 512 + hb * 32;
        #pragma unroll
        for (int i = 0; i < 7; i++) {
            const int f = tid + i * ATT_THREADS;
            const int m = f >> 5, q = (f & 31) * 4;
            *(float4*)(Ks + m * 128 + q) = *(const float4*)(gk + (size_t)m * 768 + q);
            *(float4*)(Vs + m * 128 + q) = *(const float4*)(gv + (size_t)m * 768 + q);
        }
    }
    __syncthreads();

    // 1/||k|| per (h,m)
    if (tid < 196) {
        const int h = tid / NTOK, m = tid - (tid / NTOK) * NTOK;
        const float4* kp = (const float4*)(Ks + m * 128 + h * 32);
        float s0 = 0.f, s1 = 0.f, s2 = 0.f, s3 = 0.f;
        #pragma unroll
        for (int d = 0; d < 8; d++) {
            const float4 v = kp[d];
            s0 = fmaf(v.x, v.x, s0); s1 = fmaf(v.y, v.y, s1);
            s2 = fmaf(v.z, v.z, s2); s3 = fmaf(v.w, v.w, s3);
        }
        Krs[tid] = 1.0f / fmaxf(sqrtf((s0 + s1) + (s2 + s3)), 1e-12f);
    }
    __syncthreads();

    // thread mapping: pair of queries x d-half; tids >= 200 duplicate pair 99
    const int pair0 = tid >> 1;
    const int pair  = (pair0 < 100) ? pair0 : 99;
    const int dh    = tid & 1;
    const int h     = pair / 25;
    const int qp    = pair - h * 25;
    const int q0    = qp * 2;
    const int q1r   = (q0 + 1 < NTOK) ? q0 + 1 : NTOK - 1;  // clamped load row
    const bool act  = (pair0 < 100);
    const bool v1   = act && (q0 + 1 < NTOK);
    const int hg    = hb + h;

    // load + normalize the two q half-rows (full norm via partner shfl)
    unsigned long long qq0[8], qq1[8];
    {
        const float4* qa = (const float4*)(g_qkv + base + (size_t)q0 * 768 + hg * 32 + dh * 16);
        const float4* qc = (const float4*)(g_qkv + base + (size_t)q1r * 768 + hg * 32 + dh * 16);
        float4 a[4], c[4];
        float s0 = 0.f, s1 = 0.f;
        #pragma unroll
        for (int d = 0; d < 4; d++) {
            a[d] = qa[d];
            s0 = fmaf(a[d].x, a[d].x, fmaf(a[d].y, a[d].y,
                 fmaf(a[d].z, a[d].z, fmaf(a[d].w, a[d].w, s0))));
            c[d] = qc[d];
            s1 = fmaf(c[d].x, c[d].x, fmaf(c[d].y, c[d].y,
                 fmaf(c[d].z, c[d].z, fmaf(c[d].w, c[d].w, s1))));
        }
        s0 += __shfl_xor_sync(0xFFFFFFFFu, s0, 1);
        s1 += __shfl_xor_sync(0xFFFFFFFFu, s1, 1);
        const float lsc = __expf(fminf(logit_scale[hg], 4.6051701859880914f));
        const float i0 = lsc / fmaxf(sqrtf(s0), 1e-12f);
        const float i1 = lsc / fmaxf(sqrtf(s1), 1e-12f);
        #pragma unroll
        for (int d = 0; d < 4; d++) {
            qq0[2 * d]     = pack2(a[d].x * i0, a[d].y * i0);
            qq0[2 * d + 1] = pack2(a[d].z * i0, a[d].w * i0);
            qq1[2 * d]     = pack2(c[d].x * i1, c[d].y * i1);
            qq1[2 * d + 1] = pack2(c[d].z * i1, c[d].w * i1);
        }
    }

    const float* krp = Krs + h * NTOK;
    const float* cbb = g_cbias + ((size_t)(b & 63) * 8 + hg) * (49 * 50) + q0;
    float* arow_own  = arowb + (pair * 2 + dh) * NTOK;

    // QK pass: half-d partial dots, combine with partner, store logits
    float mx0 = -1e30f, mx1 = -1e30f;
    #pragma unroll 7
    for (int m = 0; m < NTOK; m++) {
        const ulonglong2* k4 = (const ulonglong2*)(Ks + m * 128 + h * 32 + dh * 16);
        unsigned long long a0 = 0ULL, a1 = 0ULL, c0 = 0ULL, c1 = 0ULL;
        #pragma unroll
        for (int j = 0; j < 2; j++) {
            const ulonglong2 kA = k4[2 * j], kB = k4[2 * j + 1];
            ffma2(a0, qq0[4 * j],     kA.x); ffma2(a1, qq0[4 * j + 1], kA.y);
            ffma2(a0, qq0[4 * j + 2], kB.x); ffma2(a1, qq0[4 * j + 3], kB.y);
            ffma2(c0, qq1[4 * j],     kA.x); ffma2(c1, qq1[4 * j + 1], kA.y);
            ffma2(c0, qq1[4 * j + 2], kB.x); ffma2(c1, qq1[4 * j + 3], kB.y);
        }
        float x0, x1, x2, x3;
        unpack2(a0, x0, x1); unpack2(a1, x2, x3);
        float p0 = (x0 + x1) + (x2 + x3);
        unpack2(c0, x0, x1); unpack2(c1, x2, x3);
        float p1 = (x0 + x1) + (x2 + x3);
        p0 += __shfl_xor_sync(0xFFFFFFFFu, p0, 1);
        p1 += __shfl_xor_sync(0xFFFFFFFFu, p1, 1);
        const float2 cb2 = *(const float2*)(cbb + m * 50);
        const float kr = krp[m];
        const float l0 = p0 * kr + cb2.x;
        const float l1 = p1 * kr + cb2.y;
        arow_own[m] = dh ? l1 : l0;
        mx0 = fmaxf(mx0, l0);
        mx1 = fmaxf(mx1, l1);
    }

    // AV pass: exp own query, exchange, accumulate both queries' half-d outputs
    const float mxo = dh ? mx1 : mx0;
    float ss0 = 0.f, ss1 = 0.f;
    unsigned long long o20[8], o21[8];
    #pragma unroll
    for (int j = 0; j < 8; j++) { o20[j] = 0ULL; o21[j] = 0ULL; }
    #pragma unroll 7
    for (int m = 0; m < NTOK; m++) {
        const float eo = fexp(arow_own[m] - mxo);
        const float ex = __shfl_xor_sync(0xFFFFFFFFu, eo, 1);
        const float e0 = dh ? ex : eo;
        const float e1 = dh ? eo : ex;
        ss0 += e0; ss1 += e1;
        const ulonglong2* v4 = (const ulonglong2*)(Vs + m * 128 + h * 32 + dh * 16);
        const unsigned long long pp0 = pack2(e0, e0);
        const unsigned long long pp1 = pack2(e1, e1);
        #pragma unroll
        for (int j = 0; j < 2; j++) {
            const ulonglong2 vA = v4[2 * j], vB = v4[2 * j + 1];
            ffma2(o20[4 * j],     pp0, vA.x); ffma2(o20[4 * j + 1], pp0, vA.y);
            ffma2(o20[4 * j + 2], pp0, vB.x); ffma2(o20[4 * j + 3], pp0, vB.y);
            ffma2(o21[4 * j],     pp1, vA.x); ffma2(o21[4 * j + 1], pp1, vA.y);
            ffma2(o21[4 * j + 2], pp1, vB.x); ffma2(o21[4 * j + 3], pp1, vB.y);
        }
    }

    // write bf16 [hi|lo|hi] half-rows into the proj GEMM's A matrix
    const float r0 = 1.0f / ss0;
    const float r1 = 1.0f / ss1;
    #pragma unroll
    for (int qi = 0; qi < 2; qi++) {
        const bool ok = qi ? v1 : act;
        if (!ok) continue;
        const unsigned long long* o2 = qi ? o21 : o20;
        const float rv = qi ? r1 : r0;
        const int q = q0 + qi;
        __nv_bfloat16* dst = g_abig + ((size_t)b * NTOK + q) * KTOT + hg * 32 + dh * 16;
        uint32_t hv[8], lv[8];
        #pragma unroll
        for (int j = 0; j < 8; j++) {
            float x0, x1;
            unpack2(o2[j], x0, x1);
            x0 *= rv; x1 *= rv;
            const __nv_bfloat162 hp = __floats2bfloat162_rn(x0, x1);
            const __nv_bfloat162 lp = __floats2bfloat162_rn(x0 - __bfloat162float(hp.x),
                                                            x1 - __bfloat162float(hp.y));
            hv[j] = *(const uint32_t*)&hp;
            lv[j] = *(const uint32_t*)&lp;
        }
        const uint4 H0 = make_uint4(hv[0], hv[1], hv[2], hv[3]);
        const uint4 H1 = make_uint4(hv[4], hv[5], hv[6], hv[7]);
        const uint4 L0 = make_uint4(lv[0], lv[1], lv[2], lv[3]);
        const uint4 L1 = make_uint4(lv[4], lv[5], lv[6], lv[7]);
        *(uint4*)(dst)           = H0;
        *(uint4*)(dst + 8)       = H1;
        *(uint4*)(dst + 256)     = L0;
        *(uint4*)(dst + 256 + 8) = L1;
        *(uint4*)(dst + 512)     = H0;
        *(uint4*)(dst + 512 + 8) = H1;
    }
}

// ---------------- launch ----------------------------------------------------------
extern "C" void kernel_launch(void* const* d_in, const int* in_sizes, int n_in,
                              void* d_out, int out_size)
{
    const float* x    = (const float*)d_in[0];
    const float* mask = (const float*)d_in[1];
    const float* qkvw = (const float*)d_in[2];
    const float* qb   = (const float*)d_in[3];
    const float* vb   = (const float*)d_in[4];
    const float* ls   = (const float*)d_in[5];
    const float* w1   = (const float*)d_in[6];
    const float* b1   = (const float*)d_in[7];
    const float* w2   = (const float*)d_in[8];
    const float* pw   = (const float*)d_in[9];
    const float* pb   = (const float*)d_in[10];
    const float* rct  = (const float*)d_in[11];
    const int*   rpi  = (const int*)d_in[12];
    float* out = (float*)d_out;

    const int attn_smem = ATT_SMEMF * 4;   // 90160 B
    cudaFuncSetAttribute(attn_kernel, cudaFuncAttributeMaxDynamicSharedMemorySize, attn_smem);

    const int nbias = (64 * 8 * 49 * 50) / 256;   // 4900 tail blocks

    prep_kernel<<<1, 256>>>(rct, w1, b1, w2, qb, vb);
    conv_kernel<<<25088 + 1024, 256>>>(x, qkvw, pw);
    gemm_mma<<<6 * 784 + nbias, 256>>>(nullptr, nullptr, 0, rpi, mask);
    attn_kernel<<<WNUM * 2, ATT_THREADS, attn_smem>>>(ls);          // <- profiled
    gemm_mma<<<2 * 784, 256>>>(pb, out, 1, nullptr, nullptr);
}